// round 14
// baseline (speedup 1.0000x reference)
#include <cuda_runtime.h>
#include <cuda_fp16.h>
#include <cuda_bf16.h>

#define NP 100000
#define ND 30000
#define NM 20000
#define EE 600000
#define ELN 200000
#define HD 128
#define CD 64

// CSR segment layout (patient chains first):
// [dp: NP rows][mp: NP rows][pd: ND rows][pm: NM rows]
// srcs bases: dp+mp -> [0, 2EE), pd -> [2EE, 3EE), pm -> [3EE, 4EE)
#define TOT    (2 * NP + ND + NM)           // 250000
#define NBLK_P  ((2 * NP + 1023) / 1024)    // 196
#define NBLK_PD ((ND + 1023) / 1024)        // 30
#define NBLK_PM ((NM + 1023) / 1024)        // 20

// ---------------- static device scratch ----------------
__device__ __align__(256) int g_cnt[TOT];
__device__ __align__(256) int g_rowptr[TOT + 1];
__device__ __align__(256) int g_wp[TOT];
__device__ __align__(256) int g_bsum[NBLK_P];
__device__ __align__(256) int g_bexcl[NBLK_P];
__device__ __align__(256) int g_srcs[4 * EE];

__device__ __align__(256) __half g_xh[(NP + ND + NM) * HD];  // fp16 embeddings
__device__ __align__(256) __half g_wt[4 * HD * HD];          // fp16 transposed W1s[et]
__device__ __align__(256) __half g_hspc[NP * 256];  // [hs0: x_p@W1s0][hs2: x_p@W1s2]
__device__ __align__(256) __half g_hsd [ND * HD];
__device__ __align__(256) __half g_hsm [NM * HD];
__device__ __align__(256) float g_vec[16 * HD];
__device__ __align__(256) float g_u[3 * HD];
__device__ __align__(256) float g_cb[2];
// L1 attention scalars (from raw embeddings)
__device__ __align__(256) float g_as0[NP], g_ad1[NP], g_as2[NP], g_ad3[NP];
__device__ __align__(256) float g_ad0[ND], g_as1[ND];
__device__ __align__(256) float g_ad2[NM], g_as3[NM];
// L2 attention scalars + h.u dots (from fused agg)
__device__ __align__(256) float g_as1b[ND], g_hwd[ND];
__device__ __align__(256) float g_ad2b[NM], g_as3b[NM], g_hwm[NM];
__device__ __align__(256) float g_ad1b[NP], g_as2b[NP], g_ad3b[NP], g_hwp[NP];
__device__ __align__(256) float g_sp[NP], g_sm[NM];

// ---------------- helpers ----------------
__device__ __forceinline__ float warp_sum(float v) {
    #pragma unroll
    for (int o = 16; o; o >>= 1) v += __shfl_down_sync(0xFFFFFFFFu, v, o);
    return v;
}
__device__ __forceinline__ float dot4(float4 a, float4 b) {
    return a.x * b.x + a.y * b.y + a.z * b.z + a.w * b.w;
}

// ---------------- prep kernels ----------------
__global__ void k_cvt(const float4* __restrict__ x, uint2* __restrict__ o, int n4) {
    int i = blockIdx.x * blockDim.x + threadIdx.x;
    if (i >= n4) return;
    float4 v = x[i];
    __half2 lo = __floats2half2_rn(v.x, v.y);
    __half2 hi = __floats2half2_rn(v.z, v.w);
    uint2 r;
    r.x = *(unsigned*)&lo;
    r.y = *(unsigned*)&hi;
    o[i] = r;
}

// WT[n][k] = fp16(W[k][n]);  W: [128][128] fp32 row-major (k-major)
__global__ void k_cvtW(const float* __restrict__ W, __half* __restrict__ WT) {
    int i = blockIdx.x * blockDim.x + threadIdx.x;   // 16384
    int n = i >> 7, k = i & 127;
    WT[(size_t)n * HD + k] = __float2half_rn(W[(size_t)k * HD + n]);
}

__global__ void k_make_vecs(const float* __restrict__ Ws, const float* __restrict__ as_,
                            const float* __restrict__ Wd, const float* __restrict__ ad_,
                            float* __restrict__ out, int net, int Co) {
    int idx = blockIdx.x * blockDim.x + threadIdx.x;
    if (idx >= net * 2 * HD) return;
    int k = idx % HD;
    int w = (idx / HD) & 1;
    int et = idx / (2 * HD);
    const float* W = w ? Wd : Ws;
    const float* a = w ? ad_ : as_;
    const float* Wrow = W + (size_t)et * HD * Co + (size_t)k * Co;
    const float* av = a + (size_t)et * Co;
    float s = 0.f;
    for (int j = 0; j < Co; j++) s += Wrow[j] * av[j];
    out[idx] = s;
}

__global__ void k_uvecs(const float* __restrict__ W2s, const float* __restrict__ linw,
                        float* __restrict__ u) {
    int idx = blockIdx.x * blockDim.x + threadIdx.x;
    if (idx >= 3 * HD) return;
    int e = idx / HD, k = idx % HD;
    const float* W = W2s + (size_t)(e + 1) * HD * CD + (size_t)k * CD;
    const float* w = linw + ((e == 1) ? CD : 0);
    float s = 0.f;
    for (int j = 0; j < CD; j++) s += W[j] * w[j];
    u[idx] = s;
}

__global__ void k_consts(const float* __restrict__ b2, const float* __restrict__ linw,
                         float* __restrict__ cb) {
    int lane = threadIdx.x & 31, w = threadIdx.x >> 5;
    float s;
    if (w == 0) {
        s = (b2[1 * CD + lane] + b2[3 * CD + lane]) * linw[lane]
          + (b2[1 * CD + lane + 32] + b2[3 * CD + lane + 32]) * linw[lane + 32];
    } else {
        s = b2[2 * CD + lane] * linw[CD + lane]
          + b2[2 * CD + lane + 32] * linw[CD + lane + 32];
    }
    s = warp_sum(s);
    if (lane == 0) cb[w] = s;
}

// DIM=128: one float4 per lane per operand
__global__ void k_multi_dot4(const float4* __restrict__ x, int N,
                             const float4* __restrict__ v0, const float4* __restrict__ v1,
                             const float4* __restrict__ v2, const float4* __restrict__ v3,
                             float* __restrict__ o0, float* __restrict__ o1,
                             float* __restrict__ o2, float* __restrict__ o3) {
    int warp = (blockIdx.x * blockDim.x + threadIdx.x) >> 5;
    int lane = threadIdx.x & 31;
    if (warp >= N) return;
    float4 xv = __ldg(x + (size_t)warp * 32 + lane);
    float s0 = dot4(xv, __ldg(v0 + lane));
    float s1 = v1 ? dot4(xv, __ldg(v1 + lane)) : 0.f;
    float s2 = v2 ? dot4(xv, __ldg(v2 + lane)) : 0.f;
    float s3 = v3 ? dot4(xv, __ldg(v3 + lane)) : 0.f;
    s0 = warp_sum(s0);
    if (v1) s1 = warp_sum(s1);
    if (v2) s2 = warp_sum(s2);
    if (v3) s3 = warp_sum(s3);
    if (lane == 0) {
        o0[warp] = s0;
        if (o1) o1[warp] = s1;
        if (o2) o2[warp] = s2;
        if (o3) o3[warp] = s3;
    }
}

// ---------------- CSR build (3 independent chains) ----------------
// chain hist over two relations (dst2 rows offset by rows1)
__global__ void k_hist2(const int* __restrict__ d1, const int* __restrict__ d2,
                        int* __restrict__ cnt, int rows1) {
    int idx = blockIdx.x * blockDim.x + threadIdx.x;
    if (idx >= 2 * EE) return;
    int r = idx >= EE;
    int e = idx - (r ? EE : 0);
    int d = r ? d2[e] + rows1 : d1[e];
    atomicAdd(cnt + d, 1);
}

__global__ void k_hist1(const int* __restrict__ d1, int* __restrict__ cnt) {
    int idx = blockIdx.x * blockDim.x + threadIdx.x;
    if (idx >= EE) return;
    atomicAdd(cnt + d1[idx], 1);
}

__global__ void k_scan1(const int* __restrict__ cnt, int* __restrict__ rp,
                        int* __restrict__ bsum, int N) {
    __shared__ int sh[1024];
    int t = threadIdx.x;
    int i = blockIdx.x * 1024 + t;
    int v = (i < N) ? cnt[i] : 0;
    sh[t] = v;
    __syncthreads();
    for (int o = 1; o < 1024; o <<= 1) {
        int x = (t >= o) ? sh[t - o] : 0;
        __syncthreads();
        sh[t] += x;
        __syncthreads();
    }
    if (i < N) rp[i] = sh[t] - v;
    if (t == 1023) bsum[blockIdx.x] = sh[1023];
}

__global__ void k_scan2(const int* __restrict__ bsum, int* __restrict__ bexcl, int nblk) {
    __shared__ int sh[256];
    int t = threadIdx.x;
    int v = (t < nblk) ? bsum[t] : 0;
    sh[t] = v;
    __syncthreads();
    for (int o = 1; o < 256; o <<= 1) {
        int x = (t >= o) ? sh[t - o] : 0;
        __syncthreads();
        sh[t] += x;
        __syncthreads();
    }
    if (t < nblk) bexcl[t] = sh[t] - v;
}

// adds block offsets + global srcs base, writes wp copy, writes end boundary
__global__ void k_scan3(int* __restrict__ rp, const int* __restrict__ bexcl,
                        int* __restrict__ wp, int N, int base, int total) {
    int i = blockIdx.x * 1024 + threadIdx.x;
    if (i < N) {
        int v = rp[i] + bexcl[blockIdx.x] + base;
        rp[i] = v;
        wp[i] = v;
    }
    if (i == 0) rp[N] = base + total;
}

__global__ void k_fill2(const int* __restrict__ s1, const int* __restrict__ d1,
                        const int* __restrict__ s2, const int* __restrict__ d2,
                        int* __restrict__ wp, int* __restrict__ srcs, int rows1) {
    int idx = blockIdx.x * blockDim.x + threadIdx.x;
    if (idx >= 2 * EE) return;
    int r = idx >= EE;
    int e = idx - (r ? EE : 0);
    int d = r ? d2[e] + rows1 : d1[e];
    int s = r ? s2[e] : s1[e];
    int pos = atomicAdd(wp + d, 1);
    srcs[pos] = s;
}

__global__ void k_fill1(const int* __restrict__ s1, const int* __restrict__ d1,
                        int* __restrict__ wp, int* __restrict__ srcs) {
    int idx = blockIdx.x * blockDim.x + threadIdx.x;
    if (idx >= EE) return;
    int pos = atomicAdd(wp + d1[idx], 1);
    srcs[pos] = s1[idx];
}

// ---------------- fp16 GEMM: C[M,64/block] = A[M,128] @ WT^T, mma m16n8k16 ----------------
__device__ __forceinline__ void mma_f16(float* d, const unsigned* a, const unsigned* b) {
    asm volatile(
        "mma.sync.aligned.m16n8k16.row.col.f32.f16.f16.f32 "
        "{%0,%1,%2,%3}, {%4,%5,%6,%7}, {%8,%9}, {%0,%1,%2,%3};"
        : "+f"(d[0]), "+f"(d[1]), "+f"(d[2]), "+f"(d[3])
        : "r"(a[0]), "r"(a[1]), "r"(a[2]), "r"(a[3]), "r"(b[0]), "r"(b[1]));
}

__global__ __launch_bounds__(256) void k_gemm_f16(const __half* __restrict__ A,
                                                  const __half* __restrict__ WT,
                                                  __half* __restrict__ C,
                                                  int M, int ldc) {
    __shared__ __half As[2][128][40];    // u32 bank (20r + t) % 32: conflict-free
    __shared__ __half Bsn[2][64][40];    // [n][k]
    int tid = threadIdx.x;
    int lane = tid & 31, warp = tid >> 5;
    int gid = lane >> 2, tig = lane & 3;
    int wm = warp & 3, wn = warp >> 2;
    int m0 = blockIdx.x * 128, n0 = blockIdx.y * 64;

    float acc[2][4][4];
    #pragma unroll
    for (int i = 0; i < 2; i++)
        #pragma unroll
        for (int j = 0; j < 4; j++)
            #pragma unroll
            for (int l = 0; l < 4; l++) acc[i][j][l] = 0.f;

    auto load_stage = [&](int kb, int buf) {
        #pragma unroll
        for (int i = 0; i < 2; i++) {
            int f = i * 256 + tid;          // 0..511
            int m = f >> 2;
            int c8 = (f & 3) * 8;
            const __half* src = A + (size_t)(m0 + m) * 128 + kb * 32 + c8;
            unsigned ds = (unsigned)__cvta_generic_to_shared(&As[buf][m][c8]);
            int p = (m0 + m < M) ? 16 : 0;
            asm volatile("cp.async.cg.shared.global [%0], [%1], 16, %2;"
                         :: "r"(ds), "l"(src), "r"(p));
        }
        {
            int n = tid >> 2;                // 0..63
            int c8 = (tid & 3) * 8;
            const __half* src = WT + (size_t)(n0 + n) * 128 + kb * 32 + c8;
            unsigned ds = (unsigned)__cvta_generic_to_shared(&Bsn[buf][n][c8]);
            asm volatile("cp.async.cg.shared.global [%0], [%1], 16, 16;"
                         :: "r"(ds), "l"(src));
        }
        asm volatile("cp.async.commit_group;");
    };

    load_stage(0, 0);

    for (int kb = 0; kb < 4; kb++) {
        if (kb < 3) {
            load_stage(kb + 1, (kb + 1) & 1);
            asm volatile("cp.async.wait_group 1;");
        } else {
            asm volatile("cp.async.wait_group 0;");
        }
        __syncthreads();
        int buf = kb & 1;
        #pragma unroll
        for (int ks = 0; ks < 2; ks++) {
            int kk = ks * 16;
            unsigned a[2][4], b[4][2];
            #pragma unroll
            for (int ms = 0; ms < 2; ms++) {
                int r = wm * 32 + ms * 16 + gid;
                a[ms][0] = *(const unsigned*)&As[buf][r][kk + tig * 2];
                a[ms][1] = *(const unsigned*)&As[buf][r + 8][kk + tig * 2];
                a[ms][2] = *(const unsigned*)&As[buf][r][kk + 8 + tig * 2];
                a[ms][3] = *(const unsigned*)&As[buf][r + 8][kk + 8 + tig * 2];
            }
            #pragma unroll
            for (int ns = 0; ns < 4; ns++) {
                int c = wn * 32 + ns * 8 + gid;
                b[ns][0] = *(const unsigned*)&Bsn[buf][c][kk + tig * 2];
                b[ns][1] = *(const unsigned*)&Bsn[buf][c][kk + 8 + tig * 2];
            }
            #pragma unroll
            for (int ms = 0; ms < 2; ms++)
                #pragma unroll
                for (int ns = 0; ns < 4; ns++) mma_f16(acc[ms][ns], a[ms], b[ns]);
        }
        __syncthreads();
    }

    #pragma unroll
    for (int ms = 0; ms < 2; ms++) {
        int r = m0 + wm * 32 + ms * 16 + gid;
        #pragma unroll
        for (int ns = 0; ns < 4; ns++) {
            int c = n0 + wn * 32 + ns * 8 + 2 * tig;
            if (r < M)
                *(__half2*)(C + (size_t)r * ldc + c) = __floats2half2_rn(acc[ms][ns][0], acc[ms][ns][1]);
            if (r + 8 < M)
                *(__half2*)(C + (size_t)(r + 8) * ldc + c) = __floats2half2_rn(acc[ms][ns][2], acc[ms][ns][3]);
        }
    }
}

// ---------------- agg segment: shuffle-broadcast indices + 2-stage pipeline ----------------
__device__ __forceinline__ void agg_segment(
    int b, int e, const int* __restrict__ srcs,
    const float* __restrict__ as_, float adv,
    const uint4* __restrict__ hs, int srow, int soff,
    int lane, int half, int l16, float* acc, float& den)
{
    for (int c0 = b; c0 < e; c0 += 32) {
        int idx = c0 + lane;
        int sv = (idx < e) ? __ldg(srcs + idx) : 0;   // coalesced index chunk
        int cnt = min(32, e - c0);
        int s_c = __shfl_sync(0xFFFFFFFFu, sv, min(half, cnt - 1));
        float a_c = __ldg(as_ + s_c);
        uint4 h_c = __ldg(hs + (size_t)s_c * srow + soff + l16);
        for (int t2 = 0; t2 < cnt; t2 += 2) {
            int t2n = t2 + 2;
            int sh = (t2n < cnt) ? min(t2n + half, cnt - 1) : 0;
            int s_n = __shfl_sync(0xFFFFFFFFu, sv, sh);
            float a_n = __ldg(as_ + s_n);
            uint4 h_n = __ldg(hs + (size_t)s_n * srow + soff + l16);
            float x = a_c + adv;
            x = (x >= 0.f) ? x : 0.2f * x;
            float ex = (t2 + half < cnt) ? __expf(x) : 0.f;
            den += ex;
            float2 f0 = __half22float2(*(__half2*)&h_c.x);
            float2 f1 = __half22float2(*(__half2*)&h_c.y);
            float2 f2 = __half22float2(*(__half2*)&h_c.z);
            float2 f3 = __half22float2(*(__half2*)&h_c.w);
            acc[0] += ex * f0.x; acc[1] += ex * f0.y;
            acc[2] += ex * f1.x; acc[3] += ex * f1.y;
            acc[4] += ex * f2.x; acc[5] += ex * f2.y;
            acc[6] += ex * f3.x; acc[7] += ex * f3.y;
            s_c = s_n; a_c = a_n; h_c = h_n;
        }
    }
}

// ---------------- fused L1 aggregation: gather + softmax + relu + dots ----------------
template<int NV, bool DUAL>
__global__ __launch_bounds__(256) void k_agg_dot(
    const int* __restrict__ rpA, const int* __restrict__ rpB,
    const int* __restrict__ srcs,
    const float* __restrict__ asA, const float* __restrict__ adA,
    const float* __restrict__ asB, const float* __restrict__ adB,
    const uint4* __restrict__ hsA, int srowA, int soffA,
    const uint4* __restrict__ hsB, int srowB, int soffB,
    const float* __restrict__ ba, const float* __restrict__ bb,
    const float* __restrict__ v0, const float* __restrict__ v1,
    const float* __restrict__ v2, const float* __restrict__ v3,
    float* __restrict__ o0, float* __restrict__ o1,
    float* __restrict__ o2, float* __restrict__ o3, int N)
{
    int n = (blockIdx.x * blockDim.x + threadIdx.x) >> 5;
    int lane = threadIdx.x & 31;
    if (n >= N) return;
    int half = lane >> 4, l16 = lane & 15;

    float acc[8], den = 0.f;
    #pragma unroll
    for (int i = 0; i < 8; i++) acc[i] = 0.f;
    agg_segment(rpA[n], rpA[n + 1], srcs, asA, adA[n], hsA, srowA, soffA,
                lane, half, l16, acc, den);

    float accB[8], denB = 0.f;
    if (DUAL) {
        #pragma unroll
        for (int i = 0; i < 8; i++) accB[i] = 0.f;
        agg_segment(rpB[n], rpB[n + 1], srcs, asB, adB[n], hsB, srowB, soffB,
                    lane, half, l16, accB, denB);
    }

    #pragma unroll
    for (int i = 0; i < 8; i++) acc[i] += __shfl_down_sync(0xFFFFFFFFu, acc[i], 16);
    den += __shfl_down_sync(0xFFFFFFFFu, den, 16);
    if (DUAL) {
        #pragma unroll
        for (int i = 0; i < 8; i++) accB[i] += __shfl_down_sync(0xFFFFFFFFu, accB[i], 16);
        denB += __shfl_down_sync(0xFFFFFFFFu, denB, 16);
    }

    float r = (den > 0.f) ? 1.f / den : 0.f;
    float4 bv0 = __ldg((const float4*)ba + l16 * 2);
    float4 bv1 = __ldg((const float4*)ba + l16 * 2 + 1);
    float h[8];
    h[0] = acc[0] * r + bv0.x; h[1] = acc[1] * r + bv0.y;
    h[2] = acc[2] * r + bv0.z; h[3] = acc[3] * r + bv0.w;
    h[4] = acc[4] * r + bv1.x; h[5] = acc[5] * r + bv1.y;
    h[6] = acc[6] * r + bv1.z; h[7] = acc[7] * r + bv1.w;
    if (DUAL) {
        float rB = (denB > 0.f) ? 1.f / denB : 0.f;
        float4 c0 = __ldg((const float4*)bb + l16 * 2);
        float4 c1 = __ldg((const float4*)bb + l16 * 2 + 1);
        h[0] += accB[0] * rB + c0.x; h[1] += accB[1] * rB + c0.y;
        h[2] += accB[2] * rB + c0.z; h[3] += accB[3] * rB + c0.w;
        h[4] += accB[4] * rB + c1.x; h[5] += accB[5] * rB + c1.y;
        h[6] += accB[6] * rB + c1.z; h[7] += accB[7] * rB + c1.w;
    }
    #pragma unroll
    for (int i = 0; i < 8; i++) h[i] = fmaxf(h[i], 0.f);

    float s0 = 0.f, s1 = 0.f, s2 = 0.f, s3 = 0.f;
    {
        float4 a = __ldg((const float4*)v0 + l16 * 2);
        float4 b = __ldg((const float4*)v0 + l16 * 2 + 1);
        s0 = h[0]*a.x + h[1]*a.y + h[2]*a.z + h[3]*a.w
           + h[4]*b.x + h[5]*b.y + h[6]*b.z + h[7]*b.w;
    }
    if (NV > 1) {
        float4 a = __ldg((const float4*)v1 + l16 * 2);
        float4 b = __ldg((const float4*)v1 + l16 * 2 + 1);
        s1 = h[0]*a.x + h[1]*a.y + h[2]*a.z + h[3]*a.w
           + h[4]*b.x + h[5]*b.y + h[6]*b.z + h[7]*b.w;
    }
    if (NV > 2) {
        float4 a = __ldg((const float4*)v2 + l16 * 2);
        float4 b = __ldg((const float4*)v2 + l16 * 2 + 1);
        s2 = h[0]*a.x + h[1]*a.y + h[2]*a.z + h[3]*a.w
           + h[4]*b.x + h[5]*b.y + h[6]*b.z + h[7]*b.w;
    }
    if (NV > 3) {
        float4 a = __ldg((const float4*)v3 + l16 * 2);
        float4 b = __ldg((const float4*)v3 + l16 * 2 + 1);
        s3 = h[0]*a.x + h[1]*a.y + h[2]*a.z + h[3]*a.w
           + h[4]*b.x + h[5]*b.y + h[6]*b.z + h[7]*b.w;
    }
    #pragma unroll
    for (int o = 8; o; o >>= 1) {
        s0 += __shfl_down_sync(0xFFFFFFFFu, s0, o, 16);
        if (NV > 1) s1 += __shfl_down_sync(0xFFFFFFFFu, s1, o, 16);
        if (NV > 2) s2 += __shfl_down_sync(0xFFFFFFFFu, s2, o, 16);
        if (NV > 3) s3 += __shfl_down_sync(0xFFFFFFFFu, s3, o, 16);
    }
    if (lane == 0) {
        o0[n] = s0;
        if (NV > 1) o1[n] = s1;
        if (NV > 2) o2[n] = s2;
        if (NV > 3) o3[n] = s3;
    }
}

// ---------------- L2 scalar aggregation (gather, no atomics) ----------------
__global__ void k_s2_p(const int* __restrict__ rp1, const int* __restrict__ rp3,
                       const int* __restrict__ srcs,
                       const float* __restrict__ as1, const float* __restrict__ ad1,
                       const float* __restrict__ hw1,
                       const float* __restrict__ as3, const float* __restrict__ ad3,
                       const float* __restrict__ hw3,
                       const float* __restrict__ cb, float* __restrict__ o, int N) {
    int n = (blockIdx.x * blockDim.x + threadIdx.x) >> 5;
    int lane = threadIdx.x & 31;
    if (n >= N) return;
    float n1 = 0.f, d1 = 0.f, n3 = 0.f, d3 = 0.f;
    float a1 = ad1[n], a3 = ad3[n];
    int b = rp1[n], e = rp1[n + 1];
    for (int j = b + lane; j < e; j += 32) {
        int s = __ldg(srcs + j);
        float x = __ldg(as1 + s) + a1;
        x = (x >= 0.f) ? x : 0.2f * x;
        float ex = __expf(x);
        d1 += ex; n1 += ex * __ldg(hw1 + s);
    }
    b = rp3[n]; e = rp3[n + 1];
    for (int j = b + lane; j < e; j += 32) {
        int s = __ldg(srcs + j);
        float x = __ldg(as3 + s) + a3;
        x = (x >= 0.f) ? x : 0.2f * x;
        float ex = __expf(x);
        d3 += ex; n3 += ex * __ldg(hw3 + s);
    }
    n1 = warp_sum(n1); d1 = warp_sum(d1);
    n3 = warp_sum(n3); d3 = warp_sum(d3);
    if (lane == 0)
        o[n] = ((d1 > 0.f) ? n1 / d1 : 0.f) + ((d3 > 0.f) ? n3 / d3 : 0.f) + cb[0];
}

__global__ void k_s2_m(const int* __restrict__ rp, const int* __restrict__ srcs,
                       const float* __restrict__ as_, const float* __restrict__ ad_,
                       const float* __restrict__ hw,
                       const float* __restrict__ cb, float* __restrict__ o, int N) {
    int n = (blockIdx.x * blockDim.x + threadIdx.x) >> 5;
    int lane = threadIdx.x & 31;
    if (n >= N) return;
    float nm = 0.f, dn = 0.f;
    float a = ad_[n];
    int b = rp[n], e = rp[n + 1];
    for (int j = b + lane; j < e; j += 32) {
        int s = __ldg(srcs + j);
        float x = __ldg(as_ + s) + a;
        x = (x >= 0.f) ? x : 0.2f * x;
        float ex = __expf(x);
        dn += ex; nm += ex * __ldg(hw + s);
    }
    nm = warp_sum(nm); dn = warp_sum(dn);
    if (lane == 0) o[n] = ((dn > 0.f) ? nm / dn : 0.f) + cb[1];
}

__global__ void k_final(const int* __restrict__ row, const int* __restrict__ col,
                        const float* __restrict__ sp, const float* __restrict__ sm,
                        const float* __restrict__ lb, float* __restrict__ out, int n) {
    int j = blockIdx.x * blockDim.x + threadIdx.x;
    if (j < n) out[j] = sp[row[j]] + sm[col[j]] + lb[0];
}

// ---------------- host ----------------
static inline int cdiv(int a, int b) { return (a + b - 1) / b; }

extern "C" void kernel_launch(void* const* d_in, const int* in_sizes, int n_in,
                              void* d_out, int out_size) {
    const int* src_pd = (const int*)d_in[0];
    const int* dst_pd = (const int*)d_in[1];
    const int* src_dp = (const int*)d_in[2];
    const int* dst_dp = (const int*)d_in[3];
    const int* src_pm = (const int*)d_in[4];
    const int* dst_pm = (const int*)d_in[5];
    const int* src_mp = (const int*)d_in[6];
    const int* dst_mp = (const int*)d_in[7];
    const int* row    = (const int*)d_in[8];
    const int* col    = (const int*)d_in[9];
    const float* x_p  = (const float*)d_in[10];
    const float* x_d  = (const float*)d_in[11];
    const float* x_m  = (const float*)d_in[12];
    const float* W1s  = (const float*)d_in[13];
    const float* W1d  = (const float*)d_in[14];
    const float* a1s  = (const float*)d_in[15];
    const float* a1d  = (const float*)d_in[16];
    const float* b1   = (const float*)d_in[17];
    const float* W2s  = (const float*)d_in[18];
    const float* W2d  = (const float*)d_in[19];
    const float* a2s  = (const float*)d_in[20];
    const float* a2d  = (const float*)d_in[21];
    const float* b2   = (const float*)d_in[22];
    const float* linw = (const float*)d_in[23];
    const float* linb = (const float*)d_in[24];
    float* out = (float*)d_out;

    int *cnt, *rowptr, *wp, *bsum, *bexcl, *srcs;
    float *vec, *u, *cb, *sp, *sm;
    __half *xh, *wt, *hspc, *hsd, *hsm;
    float *as0, *ad1, *as2, *ad3, *ad0, *as1, *ad2, *as3;
    float *as1b, *hwd, *ad2b, *as3b, *hwm, *ad1b, *as2b, *ad3b, *hwp;
    cudaGetSymbolAddress((void**)&cnt,    g_cnt);
    cudaGetSymbolAddress((void**)&rowptr, g_rowptr);
    cudaGetSymbolAddress((void**)&wp,     g_wp);
    cudaGetSymbolAddress((void**)&bsum,   g_bsum);
    cudaGetSymbolAddress((void**)&bexcl,  g_bexcl);
    cudaGetSymbolAddress((void**)&srcs,   g_srcs);
    cudaGetSymbolAddress((void**)&xh,     g_xh);
    cudaGetSymbolAddress((void**)&wt,     g_wt);
    cudaGetSymbolAddress((void**)&hspc,   g_hspc);
    cudaGetSymbolAddress((void**)&hsd,    g_hsd);
    cudaGetSymbolAddress((void**)&hsm,    g_hsm);
    cudaGetSymbolAddress((void**)&vec,    g_vec);
    cudaGetSymbolAddress((void**)&u,      g_u);
    cudaGetSymbolAddress((void**)&cb,     g_cb);
    cudaGetSymbolAddress((void**)&sp,     g_sp);
    cudaGetSymbolAddress((void**)&sm,     g_sm);
    cudaGetSymbolAddress((void**)&as0,    g_as0);
    cudaGetSymbolAddress((void**)&ad1,    g_ad1);
    cudaGetSymbolAddress((void**)&as2,    g_as2);
    cudaGetSymbolAddress((void**)&ad3,    g_ad3);
    cudaGetSymbolAddress((void**)&ad0,    g_ad0);
    cudaGetSymbolAddress((void**)&as1,    g_as1);
    cudaGetSymbolAddress((void**)&ad2,    g_ad2);
    cudaGetSymbolAddress((void**)&as3,    g_as3);
    cudaGetSymbolAddress((void**)&as1b,   g_as1b);
    cudaGetSymbolAddress((void**)&hwd,    g_hwd);
    cudaGetSymbolAddress((void**)&ad2b,   g_ad2b);
    cudaGetSymbolAddress((void**)&as3b,   g_as3b);
    cudaGetSymbolAddress((void**)&hwm,    g_hwm);
    cudaGetSymbolAddress((void**)&ad1b,   g_ad1b);
    cudaGetSymbolAddress((void**)&as2b,   g_as2b);
    cudaGetSymbolAddress((void**)&ad3b,   g_ad3b);
    cudaGetSymbolAddress((void**)&hwp,    g_hwp);

    __half* xh_p = xh;
    __half* xh_d = xh + (size_t)NP * HD;
    __half* xh_m = xh + (size_t)(NP + ND) * HD;
    __half* hs0 = hspc;
    __half* hs2 = hspc + (size_t)NP * HD;
    __half* wt0 = wt;
    __half* wt1 = wt + 1 * HD * HD;
    __half* wt2 = wt + 2 * HD * HD;
    __half* wt3 = wt + 3 * HD * HD;

    // new segment order: [dp: NP][mp: NP][pd: ND][pm: NM]
    const int* rp_dp = rowptr;
    const int* rp_mp = rowptr + NP;
    const int* rp_pd = rowptr + 2 * NP;
    const int* rp_pm = rowptr + 2 * NP + ND;

    #define VEC(L, ET, W) (vec + (size_t)(((L) * 4 + (ET)) * 2 + (W)) * HD)

    static cudaStream_t sA = nullptr, sB = nullptr, sC = nullptr;
    static cudaEvent_t evRoot = nullptr, evAP = nullptr, evAPD = nullptr, evAPM = nullptr;
    static cudaEvent_t evMD = nullptr, evB = nullptr, evG0 = nullptr, evD = nullptr;
    if (sA == nullptr) {
        cudaStreamCreateWithFlags(&sA, cudaStreamNonBlocking);
        cudaStreamCreateWithFlags(&sB, cudaStreamNonBlocking);
        cudaStreamCreateWithFlags(&sC, cudaStreamNonBlocking);
        cudaEventCreateWithFlags(&evRoot, cudaEventDisableTiming);
        cudaEventCreateWithFlags(&evAP, cudaEventDisableTiming);
        cudaEventCreateWithFlags(&evAPD, cudaEventDisableTiming);
        cudaEventCreateWithFlags(&evAPM, cudaEventDisableTiming);
        cudaEventCreateWithFlags(&evMD, cudaEventDisableTiming);
        cudaEventCreateWithFlags(&evB, cudaEventDisableTiming);
        cudaEventCreateWithFlags(&evG0, cudaEventDisableTiming);
        cudaEventCreateWithFlags(&evD, cudaEventDisableTiming);
        k_consts<<<1, 64, 0, sA>>>(b2, linw, cb);
        k_consts<<<1, 64, 0, sB>>>(b2, linw, cb);
        k_consts<<<1, 64, 0, sC>>>(b2, linw, cb);
        cudaStreamSynchronize(sA);
        cudaStreamSynchronize(sB);
        cudaStreamSynchronize(sC);
    }

    cudaEventRecord(evRoot, 0);
    cudaStreamWaitEvent(sA, evRoot, 0);
    cudaStreamWaitEvent(sB, evRoot, 0);
    cudaStreamWaitEvent(sC, evRoot, 0);

    // ===== stream sA: CSR chains, patient (dp+mp) FIRST =====
    cudaMemsetAsync(cnt, 0, TOT * sizeof(int), sA);
    // chain P: rows [0, 2NP), srcs [0, 2EE)
    k_hist2<<<cdiv(2 * EE, 256), 256, 0, sA>>>(dst_dp, dst_mp, cnt, NP);
    k_scan1<<<NBLK_P, 1024, 0, sA>>>(cnt, rowptr, bsum, 2 * NP);
    k_scan2<<<1, 256, 0, sA>>>(bsum, bexcl, NBLK_P);
    k_scan3<<<NBLK_P, 1024, 0, sA>>>(rowptr, bexcl, wp, 2 * NP, 0, 2 * EE);
    k_fill2<<<cdiv(2 * EE, 256), 256, 0, sA>>>(src_dp, dst_dp, src_mp, dst_mp, wp, srcs, NP);
    cudaEventRecord(evAP, sA);
    // chain PD: rows [2NP, 2NP+ND), srcs [2EE, 3EE)
    k_hist1<<<cdiv(EE, 256), 256, 0, sA>>>(dst_pd, cnt + 2 * NP);
    k_scan1<<<NBLK_PD, 1024, 0, sA>>>(cnt + 2 * NP, rowptr + 2 * NP, bsum, ND);
    k_scan2<<<1, 256, 0, sA>>>(bsum, bexcl, NBLK_PD);
    k_scan3<<<NBLK_PD, 1024, 0, sA>>>(rowptr + 2 * NP, bexcl, wp + 2 * NP, ND, 2 * EE, EE);
    k_fill1<<<cdiv(EE, 256), 256, 0, sA>>>(src_pd, dst_pd, wp + 2 * NP, srcs);
    cudaEventRecord(evAPD, sA);
    // chain PM: rows [2NP+ND, TOT), srcs [3EE, 4EE)
    k_hist1<<<cdiv(EE, 256), 256, 0, sA>>>(dst_pm, cnt + 2 * NP + ND);
    k_scan1<<<NBLK_PM, 1024, 0, sA>>>(cnt + 2 * NP + ND, rowptr + 2 * NP + ND, bsum, NM);
    k_scan2<<<1, 256, 0, sA>>>(bsum, bexcl, NBLK_PM);
    k_scan3<<<NBLK_PM, 1024, 0, sA>>>(rowptr + 2 * NP + ND, bexcl, wp + 2 * NP + ND, NM, 3 * EE, EE);
    k_fill1<<<cdiv(EE, 256), 256, 0, sA>>>(src_pm, dst_pm, wp + 2 * NP + ND, srcs);
    cudaEventRecord(evAPM, sA);

    // ===== stream sC: vec prep + L1 attention scalars -> evMD, then disease agg =====
    k_make_vecs<<<cdiv(4 * 2 * HD, 256), 256, 0, sC>>>(W1s, a1s, W1d, a1d, vec, 4, HD);
    k_make_vecs<<<cdiv(4 * 2 * HD, 256), 256, 0, sC>>>(W2s, a2s, W2d, a2d, vec + 8 * HD, 4, CD);
    k_uvecs<<<2, 256, 0, sC>>>(W2s, linw, u);
    k_consts<<<1, 64, 0, sC>>>(b2, linw, cb);
    k_multi_dot4<<<cdiv(NP * 32, 256), 256, 0, sC>>>((const float4*)x_p, NP,
        (const float4*)VEC(0,0,0), (const float4*)VEC(0,1,1),
        (const float4*)VEC(0,2,0), (const float4*)VEC(0,3,1), as0, ad1, as2, ad3);
    k_multi_dot4<<<cdiv(ND * 32, 256), 256, 0, sC>>>((const float4*)x_d, ND,
        (const float4*)VEC(0,0,1), (const float4*)VEC(0,1,0),
        nullptr, nullptr, ad0, as1, nullptr, nullptr);
    k_multi_dot4<<<cdiv(NM * 32, 256), 256, 0, sC>>>((const float4*)x_m, NM,
        (const float4*)VEC(0,2,1), (const float4*)VEC(0,3,0),
        nullptr, nullptr, ad2, as3, nullptr, nullptr);
    cudaEventRecord(evMD, sC);

    // ===== main stream: self-contained patient GEMM chain =====
    k_cvtW<<<cdiv(HD * HD, 256), 256>>>(W1s + 0 * HD * HD, wt0);
    k_cvtW<<<cdiv(HD * HD, 256), 256>>>(W1s + 2 * HD * HD, wt2);
    k_cvt<<<cdiv(NP * HD / 4, 256), 256>>>((const float4*)x_p, (uint2*)xh_p, NP * HD / 4);
    {
        dim3 g1(cdiv(NP, 128), 2);
        k_gemm_f16<<<g1, 256>>>(xh_p, wt0, hs0, NP, HD);
    }
    cudaEventRecord(evG0, 0);
    {
        dim3 g1(cdiv(NP, 128), 2);
        k_gemm_f16<<<g1, 256>>>(xh_p, wt2, hs2, NP, HD);
    }

    // ===== stream sB: small-GEMM chain + patient agg (critical consumer) =====
    k_cvtW<<<cdiv(HD * HD, 256), 256, 0, sB>>>(W1s + 1 * HD * HD, wt1);
    k_cvtW<<<cdiv(HD * HD, 256), 256, 0, sB>>>(W1s + 3 * HD * HD, wt3);
    k_cvt<<<cdiv(ND * HD / 4, 256), 256, 0, sB>>>((const float4*)x_d, (uint2*)xh_d, ND * HD / 4);
    k_cvt<<<cdiv(NM * HD / 4, 256), 256, 0, sB>>>((const float4*)x_m, (uint2*)xh_m, NM * HD / 4);
    {
        dim3 g2(cdiv(ND, 128), 2);
        k_gemm_f16<<<g2, 256, 0, sB>>>(xh_d, wt1, hsd, ND, HD);
        dim3 g3(cdiv(NM, 128), 2);
        k_gemm_f16<<<g3, 256, 0, sB>>>(xh_m, wt3, hsm, NM, HD);
    }
    cudaStreamWaitEvent(sB, evAP, 0);
    cudaStreamWaitEvent(sB, evMD, 0);
    k_agg_dot<4, true><<<cdiv(NP * 32, 256), 256, 0, sB>>>(
        rp_dp, rp_mp, srcs, as1, ad1, as3, ad3,
        (const uint4*)hsd, 16, 0, (const uint4*)hsm, 16, 0,
        b1 + 1 * HD, b1 + 3 * HD,
        VEC(1,1,1), VEC(1,2,0), VEC(1,3,1), u + 1 * HD,
        ad1b, as2b, ad3b, hwp, NP);
    cudaEventRecord(evB, sB);

    // ===== stream sC: disease agg (needs GEMM0 + chain PD + multi_dots) =====
    cudaStreamWaitEvent(sC, evG0, 0);
    cudaStreamWaitEvent(sC, evAPD, 0);
    k_agg_dot<2, false><<<cdiv(ND * 32, 256), 256, 0, sC>>>(
        rp_pd, nullptr, srcs, as0, ad0, nullptr, nullptr,
        (const uint4*)hs0, 16, 0, nullptr, 0, 0,
        b1 + 0 * HD, nullptr,
        VEC(1,1,0), u + 0 * HD, nullptr, nullptr,
        as1b, hwd, nullptr, nullptr, ND);
    cudaEventRecord(evD, sC);

    // ===== main: medicine agg (needs GEMM2 + chain PM + multi_dots) =====
    cudaStreamWaitEvent(0, evAPM, 0);
    cudaStreamWaitEvent(0, evMD, 0);
    k_agg_dot<3, false><<<cdiv(NM * 32, 256), 256>>>(
        rp_pm, nullptr, srcs, as2, ad2, nullptr, nullptr,
        (const uint4*)hs2, 16, 0, nullptr, 0, 0,
        b1 + 2 * HD, nullptr,
        VEC(1,2,1), VEC(1,3,0), u + 2 * HD, nullptr,
        ad2b, as3b, hwm, nullptr, NM);

    // ===== join: L2 scalar aggregation + head =====
    cudaStreamWaitEvent(0, evB, 0);
    cudaStreamWaitEvent(0, evD, 0);
    k_s2_p<<<cdiv(NP * 32, 256), 256>>>(rp_dp, rp_mp, srcs,
        as1b, ad1b, hwd, as3b, ad3b, hwm, cb, sp, NP);
    k_s2_m<<<cdiv(NM * 32, 256), 256>>>(rp_pm, srcs, as2b, ad2b, hwp, cb, sm, NM);
    k_final<<<cdiv(ELN, 256), 256>>>(row, col, sp, sm, linb, out, ELN);
    #undef VEC
}

// round 15
// speedup vs baseline: 1.0529x; 1.0529x over previous
#include <cuda_runtime.h>
#include <cuda_fp16.h>
#include <cuda_bf16.h>

#define NP 100000
#define ND 30000
#define NM 20000
#define EE 600000
#define ELN 200000
#define HD 128
#define CD 64

// CSR segment layout over concatenated dst spaces:
// [pd: ND rows][dp: NP rows][pm: NM rows][mp: NP rows]
#define SEG_PD 0
#define SEG_DP (ND)
#define SEG_PM (ND + NP)
#define SEG_MP (ND + NP + NM)
#define TOT    (ND + NP + NM + NP)          // 250000
#define NBLK   ((TOT + 1023) / 1024)        // 245

// ---------------- static device scratch ----------------
__device__ __align__(256) int g_cnt[TOT];
__device__ __align__(256) int g_rowptr[TOT + 1];
__device__ __align__(256) int g_wp[TOT];
__device__ __align__(256) int g_bsum[NBLK];
__device__ __align__(256) int g_bexcl[NBLK];
__device__ __align__(256) int g_srcs[4 * EE];

__device__ __align__(256) __half g_xh[(NP + ND + NM) * HD];  // fp16 embeddings
__device__ __align__(256) __half g_wt[4 * HD * HD];          // fp16 transposed W1s[et]
__device__ __align__(256) __half g_hspc[NP * 256];  // [hs0: x_p@W1s0][hs2: x_p@W1s2]
__device__ __align__(256) __half g_hsd [ND * HD];
__device__ __align__(256) __half g_hsm [NM * HD];
__device__ __align__(256) float g_vec[16 * HD];
__device__ __align__(256) float g_u[3 * HD];
__device__ __align__(256) float g_cb[2];
// L1 attention scalars (from raw embeddings)
__device__ __align__(256) float g_as0[NP], g_ad1[NP], g_as2[NP], g_ad3[NP];
__device__ __align__(256) float g_ad0[ND], g_as1[ND];
__device__ __align__(256) float g_ad2[NM], g_as3[NM];
// L2 attention scalars + h.u dots (from fused agg)
__device__ __align__(256) float g_as1b[ND], g_hwd[ND];
__device__ __align__(256) float g_ad2b[NM], g_as3b[NM], g_hwm[NM];
__device__ __align__(256) float g_ad1b[NP], g_as2b[NP], g_ad3b[NP], g_hwp[NP];
__device__ __align__(256) float g_sp[NP], g_sm[NM];

// ---------------- helpers ----------------
__device__ __forceinline__ float warp_sum(float v) {
    #pragma unroll
    for (int o = 16; o; o >>= 1) v += __shfl_down_sync(0xFFFFFFFFu, v, o);
    return v;
}
__device__ __forceinline__ float dot4(float4 a, float4 b) {
    return a.x * b.x + a.y * b.y + a.z * b.z + a.w * b.w;
}

// ---------------- prep kernels ----------------
__global__ void k_cvt(const float4* __restrict__ x, uint2* __restrict__ o, int n4) {
    int i = blockIdx.x * blockDim.x + threadIdx.x;
    if (i >= n4) return;
    float4 v = x[i];
    __half2 lo = __floats2half2_rn(v.x, v.y);
    __half2 hi = __floats2half2_rn(v.z, v.w);
    uint2 r;
    r.x = *(unsigned*)&lo;
    r.y = *(unsigned*)&hi;
    o[i] = r;
}

// WT[n][k] = fp16(W[k][n]);  W: [128][128] fp32 row-major (k-major)
__global__ void k_cvtW(const float* __restrict__ W, __half* __restrict__ WT) {
    int i = blockIdx.x * blockDim.x + threadIdx.x;   // 16384
    int n = i >> 7, k = i & 127;
    WT[(size_t)n * HD + k] = __float2half_rn(W[(size_t)k * HD + n]);
}

// fused: L1 vecs [0,1024) | L2 vecs [1024,2048) | uvecs [2048,2432) | cb [2432,2434)
__global__ void k_prep(const float* __restrict__ W1s, const float* __restrict__ a1s,
                       const float* __restrict__ W1d, const float* __restrict__ a1d,
                       const float* __restrict__ W2s, const float* __restrict__ a2s,
                       const float* __restrict__ W2d, const float* __restrict__ a2d,
                       const float* __restrict__ linw, const float* __restrict__ b2,
                       float* __restrict__ vec, float* __restrict__ u,
                       float* __restrict__ cb) {
    int idx = blockIdx.x * blockDim.x + threadIdx.x;
    if (idx < 1024) {
        int k = idx % HD, w = (idx / HD) & 1, et = idx / (2 * HD);
        const float* W = w ? W1d : W1s;
        const float* a = w ? a1d : a1s;
        const float* Wrow = W + (size_t)et * HD * HD + (size_t)k * HD;
        const float* av = a + (size_t)et * HD;
        float s = 0.f;
        for (int j = 0; j < HD; j++) s += Wrow[j] * av[j];
        vec[idx] = s;
    } else if (idx < 2048) {
        int li = idx - 1024;
        int k = li % HD, w = (li / HD) & 1, et = li / (2 * HD);
        const float* W = w ? W2d : W2s;
        const float* a = w ? a2d : a2s;
        const float* Wrow = W + (size_t)et * HD * CD + (size_t)k * CD;
        const float* av = a + (size_t)et * CD;
        float s = 0.f;
        for (int j = 0; j < CD; j++) s += Wrow[j] * av[j];
        vec[8 * HD + li] = s;
    } else if (idx < 2432) {
        int li = idx - 2048;
        int e = li / HD, k = li % HD;
        const float* W = W2s + (size_t)(e + 1) * HD * CD + (size_t)k * CD;
        const float* w = linw + ((e == 1) ? CD : 0);
        float s = 0.f;
        for (int j = 0; j < CD; j++) s += W[j] * w[j];
        u[li] = s;
    } else if (idx == 2432) {
        float s = 0.f;
        for (int j = 0; j < CD; j++) s += (b2[CD + j] + b2[3 * CD + j]) * linw[j];
        cb[0] = s;
    } else if (idx == 2433) {
        float s = 0.f;
        for (int j = 0; j < CD; j++) s += b2[2 * CD + j] * linw[CD + j];
        cb[1] = s;
    }
}

__global__ void k_consts(const float* __restrict__ b2, const float* __restrict__ linw,
                         float* __restrict__ cb) {
    int lane = threadIdx.x & 31, w = threadIdx.x >> 5;
    float s;
    if (w == 0) {
        s = (b2[1 * CD + lane] + b2[3 * CD + lane]) * linw[lane]
          + (b2[1 * CD + lane + 32] + b2[3 * CD + lane + 32]) * linw[lane + 32];
    } else {
        s = b2[2 * CD + lane] * linw[CD + lane]
          + b2[2 * CD + lane + 32] * linw[CD + lane + 32];
    }
    s = warp_sum(s);
    if (lane == 0) cb[w] = s;
}

// DIM=128: one float4 per lane per operand
__global__ void k_multi_dot4(const float4* __restrict__ x, int N,
                             const float4* __restrict__ v0, const float4* __restrict__ v1,
                             const float4* __restrict__ v2, const float4* __restrict__ v3,
                             float* __restrict__ o0, float* __restrict__ o1,
                             float* __restrict__ o2, float* __restrict__ o3) {
    int warp = (blockIdx.x * blockDim.x + threadIdx.x) >> 5;
    int lane = threadIdx.x & 31;
    if (warp >= N) return;
    float4 xv = __ldg(x + (size_t)warp * 32 + lane);
    float s0 = dot4(xv, __ldg(v0 + lane));
    float s1 = v1 ? dot4(xv, __ldg(v1 + lane)) : 0.f;
    float s2 = v2 ? dot4(xv, __ldg(v2 + lane)) : 0.f;
    float s3 = v3 ? dot4(xv, __ldg(v3 + lane)) : 0.f;
    s0 = warp_sum(s0);
    if (v1) s1 = warp_sum(s1);
    if (v2) s2 = warp_sum(s2);
    if (v3) s3 = warp_sum(s3);
    if (lane == 0) {
        o0[warp] = s0;
        if (o1) o1[warp] = s1;
        if (o2) o2[warp] = s2;
        if (o3) o3[warp] = s3;
    }
}

// ---------------- CSR build ----------------
__global__ void k_hist(const int* __restrict__ d_pd, const int* __restrict__ d_dp,
                       const int* __restrict__ d_pm, const int* __restrict__ d_mp,
                       int* __restrict__ cnt) {
    int idx = blockIdx.x * blockDim.x + threadIdx.x;
    if (idx >= 4 * EE) return;
    int r = idx / EE, e = idx - r * EE;
    int d, base;
    if (r == 0)      { d = d_pd[e]; base = SEG_PD; }
    else if (r == 1) { d = d_dp[e]; base = SEG_DP; }
    else if (r == 2) { d = d_pm[e]; base = SEG_PM; }
    else             { d = d_mp[e]; base = SEG_MP; }
    atomicAdd(cnt + base + d, 1);
}

__global__ void k_scan1(const int* __restrict__ cnt, int* __restrict__ rp,
                        int* __restrict__ bsum) {
    __shared__ int sh[1024];
    int t = threadIdx.x;
    int i = blockIdx.x * 1024 + t;
    int v = (i < TOT) ? cnt[i] : 0;
    sh[t] = v;
    __syncthreads();
    for (int o = 1; o < 1024; o <<= 1) {
        int x = (t >= o) ? sh[t - o] : 0;
        __syncthreads();
        sh[t] += x;
        __syncthreads();
    }
    if (i < TOT) rp[i] = sh[t] - v;
    if (t == 1023) bsum[blockIdx.x] = sh[1023];
}

__global__ void k_scan2(const int* __restrict__ bsum, int* __restrict__ bexcl) {
    __shared__ int sh[256];
    int t = threadIdx.x;
    int v = (t < NBLK) ? bsum[t] : 0;
    sh[t] = v;
    __syncthreads();
    for (int o = 1; o < 256; o <<= 1) {
        int x = (t >= o) ? sh[t - o] : 0;
        __syncthreads();
        sh[t] += x;
        __syncthreads();
    }
    if (t < NBLK) bexcl[t] = sh[t] - v;
}

__global__ void k_scan3(int* __restrict__ rp, const int* __restrict__ bexcl,
                        int* __restrict__ wp) {
    int i = blockIdx.x * 1024 + threadIdx.x;
    if (i < TOT) {
        int v = rp[i] + bexcl[blockIdx.x];
        rp[i] = v;
        wp[i] = v;
    }
    if (i == 0) rp[TOT] = 4 * EE;
}

__global__ void k_fill(const int* __restrict__ s_pd, const int* __restrict__ d_pd,
                       const int* __restrict__ s_dp, const int* __restrict__ d_dp,
                       const int* __restrict__ s_pm, const int* __restrict__ d_pm,
                       const int* __restrict__ s_mp, const int* __restrict__ d_mp,
                       int* __restrict__ wp, int* __restrict__ srcs) {
    int idx = blockIdx.x * blockDim.x + threadIdx.x;
    if (idx >= 4 * EE) return;
    int r = idx / EE, e = idx - r * EE;
    int d, s, base;
    if (r == 0)      { d = d_pd[e]; s = s_pd[e]; base = SEG_PD; }
    else if (r == 1) { d = d_dp[e]; s = s_dp[e]; base = SEG_DP; }
    else if (r == 2) { d = d_pm[e]; s = s_pm[e]; base = SEG_PM; }
    else             { d = d_mp[e]; s = s_mp[e]; base = SEG_MP; }
    int pos = atomicAdd(wp + base + d, 1);
    srcs[pos] = s;
}

// ---------------- fp16 GEMM: C[M,64/block] = A[M,128] @ WT^T, mma m16n8k16 ----------------
__device__ __forceinline__ void mma_f16(float* d, const unsigned* a, const unsigned* b) {
    asm volatile(
        "mma.sync.aligned.m16n8k16.row.col.f32.f16.f16.f32 "
        "{%0,%1,%2,%3}, {%4,%5,%6,%7}, {%8,%9}, {%0,%1,%2,%3};"
        : "+f"(d[0]), "+f"(d[1]), "+f"(d[2]), "+f"(d[3])
        : "r"(a[0]), "r"(a[1]), "r"(a[2]), "r"(a[3]), "r"(b[0]), "r"(b[1]));
}

__global__ __launch_bounds__(256) void k_gemm_f16(const __half* __restrict__ A,
                                                  const __half* __restrict__ WT,
                                                  __half* __restrict__ C,
                                                  int M, int ldc) {
    __shared__ __half As[2][128][40];    // u32 bank (20r + t) % 32: conflict-free
    __shared__ __half Bsn[2][64][40];    // [n][k]
    int tid = threadIdx.x;
    int lane = tid & 31, warp = tid >> 5;
    int gid = lane >> 2, tig = lane & 3;
    int wm = warp & 3, wn = warp >> 2;
    int m0 = blockIdx.x * 128, n0 = blockIdx.y * 64;

    float acc[2][4][4];
    #pragma unroll
    for (int i = 0; i < 2; i++)
        #pragma unroll
        for (int j = 0; j < 4; j++)
            #pragma unroll
            for (int l = 0; l < 4; l++) acc[i][j][l] = 0.f;

    auto load_stage = [&](int kb, int buf) {
        #pragma unroll
        for (int i = 0; i < 2; i++) {
            int f = i * 256 + tid;          // 0..511
            int m = f >> 2;
            int c8 = (f & 3) * 8;
            const __half* src = A + (size_t)(m0 + m) * 128 + kb * 32 + c8;
            unsigned ds = (unsigned)__cvta_generic_to_shared(&As[buf][m][c8]);
            int p = (m0 + m < M) ? 16 : 0;
            asm volatile("cp.async.cg.shared.global [%0], [%1], 16, %2;"
                         :: "r"(ds), "l"(src), "r"(p));
        }
        {
            int n = tid >> 2;                // 0..63
            int c8 = (tid & 3) * 8;
            const __half* src = WT + (size_t)(n0 + n) * 128 + kb * 32 + c8;
            unsigned ds = (unsigned)__cvta_generic_to_shared(&Bsn[buf][n][c8]);
            asm volatile("cp.async.cg.shared.global [%0], [%1], 16, 16;"
                         :: "r"(ds), "l"(src));
        }
        asm volatile("cp.async.commit_group;");
    };

    load_stage(0, 0);

    for (int kb = 0; kb < 4; kb++) {
        if (kb < 3) {
            load_stage(kb + 1, (kb + 1) & 1);
            asm volatile("cp.async.wait_group 1;");
        } else {
            asm volatile("cp.async.wait_group 0;");
        }
        __syncthreads();
        int buf = kb & 1;
        #pragma unroll
        for (int ks = 0; ks < 2; ks++) {
            int kk = ks * 16;
            unsigned a[2][4], b[4][2];
            #pragma unroll
            for (int ms = 0; ms < 2; ms++) {
                int r = wm * 32 + ms * 16 + gid;
                a[ms][0] = *(const unsigned*)&As[buf][r][kk + tig * 2];
                a[ms][1] = *(const unsigned*)&As[buf][r + 8][kk + tig * 2];
                a[ms][2] = *(const unsigned*)&As[buf][r][kk + 8 + tig * 2];
                a[ms][3] = *(const unsigned*)&As[buf][r + 8][kk + 8 + tig * 2];
            }
            #pragma unroll
            for (int ns = 0; ns < 4; ns++) {
                int c = wn * 32 + ns * 8 + gid;
                b[ns][0] = *(const unsigned*)&Bsn[buf][c][kk + tig * 2];
                b[ns][1] = *(const unsigned*)&Bsn[buf][c][kk + 8 + tig * 2];
            }
            #pragma unroll
            for (int ms = 0; ms < 2; ms++)
                #pragma unroll
                for (int ns = 0; ns < 4; ns++) mma_f16(acc[ms][ns], a[ms], b[ns]);
        }
        __syncthreads();
    }

    #pragma unroll
    for (int ms = 0; ms < 2; ms++) {
        int r = m0 + wm * 32 + ms * 16 + gid;
        #pragma unroll
        for (int ns = 0; ns < 4; ns++) {
            int c = n0 + wn * 32 + ns * 8 + 2 * tig;
            if (r < M)
                *(__half2*)(C + (size_t)r * ldc + c) = __floats2half2_rn(acc[ms][ns][0], acc[ms][ns][1]);
            if (r + 8 < M)
                *(__half2*)(C + (size_t)(r + 8) * ldc + c) = __floats2half2_rn(acc[ms][ns][2], acc[ms][ns][3]);
        }
    }
}

// ---------------- agg segment: shuffle-broadcast indices + 2-stage pipeline ----------------
__device__ __forceinline__ void agg_segment(
    int b, int e, const int* __restrict__ srcs,
    const float* __restrict__ as_, float adv,
    const uint4* __restrict__ hs, int srow, int soff,
    int lane, int half, int l16, float* acc, float& den)
{
    for (int c0 = b; c0 < e; c0 += 32) {
        int idx = c0 + lane;
        int sv = (idx < e) ? __ldg(srcs + idx) : 0;   // coalesced index chunk
        int cnt = min(32, e - c0);
        int s_c = __shfl_sync(0xFFFFFFFFu, sv, min(half, cnt - 1));
        float a_c = __ldg(as_ + s_c);
        uint4 h_c = __ldg(hs + (size_t)s_c * srow + soff + l16);
        for (int t2 = 0; t2 < cnt; t2 += 2) {
            int t2n = t2 + 2;
            int sh = (t2n < cnt) ? min(t2n + half, cnt - 1) : 0;
            int s_n = __shfl_sync(0xFFFFFFFFu, sv, sh);
            float a_n = __ldg(as_ + s_n);
            uint4 h_n = __ldg(hs + (size_t)s_n * srow + soff + l16);
            float x = a_c + adv;
            x = (x >= 0.f) ? x : 0.2f * x;
            float ex = (t2 + half < cnt) ? __expf(x) : 0.f;
            den += ex;
            float2 f0 = __half22float2(*(__half2*)&h_c.x);
            float2 f1 = __half22float2(*(__half2*)&h_c.y);
            float2 f2 = __half22float2(*(__half2*)&h_c.z);
            float2 f3 = __half22float2(*(__half2*)&h_c.w);
            acc[0] += ex * f0.x; acc[1] += ex * f0.y;
            acc[2] += ex * f1.x; acc[3] += ex * f1.y;
            acc[4] += ex * f2.x; acc[5] += ex * f2.y;
            acc[6] += ex * f3.x; acc[7] += ex * f3.y;
            s_c = s_n; a_c = a_n; h_c = h_n;
        }
    }
}

// ---------------- fused L1 aggregation: gather + softmax + relu + dots ----------------
template<int NV, bool DUAL>
__global__ __launch_bounds__(256) void k_agg_dot(
    const int* __restrict__ rpA, const int* __restrict__ rpB,
    const int* __restrict__ srcs,
    const float* __restrict__ asA, const float* __restrict__ adA,
    const float* __restrict__ asB, const float* __restrict__ adB,
    const uint4* __restrict__ hsA, int srowA, int soffA,
    const uint4* __restrict__ hsB, int srowB, int soffB,
    const float* __restrict__ ba, const float* __restrict__ bb,
    const float* __restrict__ v0, const float* __restrict__ v1,
    const float* __restrict__ v2, const float* __restrict__ v3,
    float* __restrict__ o0, float* __restrict__ o1,
    float* __restrict__ o2, float* __restrict__ o3, int N)
{
    int n = (blockIdx.x * blockDim.x + threadIdx.x) >> 5;
    int lane = threadIdx.x & 31;
    if (n >= N) return;
    int half = lane >> 4, l16 = lane & 15;

    float acc[8], den = 0.f;
    #pragma unroll
    for (int i = 0; i < 8; i++) acc[i] = 0.f;
    agg_segment(rpA[n], rpA[n + 1], srcs, asA, adA[n], hsA, srowA, soffA,
                lane, half, l16, acc, den);

    float accB[8], denB = 0.f;
    if (DUAL) {
        #pragma unroll
        for (int i = 0; i < 8; i++) accB[i] = 0.f;
        agg_segment(rpB[n], rpB[n + 1], srcs, asB, adB[n], hsB, srowB, soffB,
                    lane, half, l16, accB, denB);
    }

    #pragma unroll
    for (int i = 0; i < 8; i++) acc[i] += __shfl_down_sync(0xFFFFFFFFu, acc[i], 16);
    den += __shfl_down_sync(0xFFFFFFFFu, den, 16);
    if (DUAL) {
        #pragma unroll
        for (int i = 0; i < 8; i++) accB[i] += __shfl_down_sync(0xFFFFFFFFu, accB[i], 16);
        denB += __shfl_down_sync(0xFFFFFFFFu, denB, 16);
    }

    float r = (den > 0.f) ? 1.f / den : 0.f;
    float4 bv0 = __ldg((const float4*)ba + l16 * 2);
    float4 bv1 = __ldg((const float4*)ba + l16 * 2 + 1);
    float h[8];
    h[0] = acc[0] * r + bv0.x; h[1] = acc[1] * r + bv0.y;
    h[2] = acc[2] * r + bv0.z; h[3] = acc[3] * r + bv0.w;
    h[4] = acc[4] * r + bv1.x; h[5] = acc[5] * r + bv1.y;
    h[6] = acc[6] * r + bv1.z; h[7] = acc[7] * r + bv1.w;
    if (DUAL) {
        float rB = (denB > 0.f) ? 1.f / denB : 0.f;
        float4 c0 = __ldg((const float4*)bb + l16 * 2);
        float4 c1 = __ldg((const float4*)bb + l16 * 2 + 1);
        h[0] += accB[0] * rB + c0.x; h[1] += accB[1] * rB + c0.y;
        h[2] += accB[2] * rB + c0.z; h[3] += accB[3] * rB + c0.w;
        h[4] += accB[4] * rB + c1.x; h[5] += accB[5] * rB + c1.y;
        h[6] += accB[6] * rB + c1.z; h[7] += accB[7] * rB + c1.w;
    }
    #pragma unroll
    for (int i = 0; i < 8; i++) h[i] = fmaxf(h[i], 0.f);

    float s0 = 0.f, s1 = 0.f, s2 = 0.f, s3 = 0.f;
    {
        float4 a = __ldg((const float4*)v0 + l16 * 2);
        float4 b = __ldg((const float4*)v0 + l16 * 2 + 1);
        s0 = h[0]*a.x + h[1]*a.y + h[2]*a.z + h[3]*a.w
           + h[4]*b.x + h[5]*b.y + h[6]*b.z + h[7]*b.w;
    }
    if (NV > 1) {
        float4 a = __ldg((const float4*)v1 + l16 * 2);
        float4 b = __ldg((const float4*)v1 + l16 * 2 + 1);
        s1 = h[0]*a.x + h[1]*a.y + h[2]*a.z + h[3]*a.w
           + h[4]*b.x + h[5]*b.y + h[6]*b.z + h[7]*b.w;
    }
    if (NV > 2) {
        float4 a = __ldg((const float4*)v2 + l16 * 2);
        float4 b = __ldg((const float4*)v2 + l16 * 2 + 1);
        s2 = h[0]*a.x + h[1]*a.y + h[2]*a.z + h[3]*a.w
           + h[4]*b.x + h[5]*b.y + h[6]*b.z + h[7]*b.w;
    }
    if (NV > 3) {
        float4 a = __ldg((const float4*)v3 + l16 * 2);
        float4 b = __ldg((const float4*)v3 + l16 * 2 + 1);
        s3 = h[0]*a.x + h[1]*a.y + h[2]*a.z + h[3]*a.w
           + h[4]*b.x + h[5]*b.y + h[6]*b.z + h[7]*b.w;
    }
    #pragma unroll
    for (int o = 8; o; o >>= 1) {
        s0 += __shfl_down_sync(0xFFFFFFFFu, s0, o, 16);
        if (NV > 1) s1 += __shfl_down_sync(0xFFFFFFFFu, s1, o, 16);
        if (NV > 2) s2 += __shfl_down_sync(0xFFFFFFFFu, s2, o, 16);
        if (NV > 3) s3 += __shfl_down_sync(0xFFFFFFFFu, s3, o, 16);
    }
    if (lane == 0) {
        o0[n] = s0;
        if (NV > 1) o1[n] = s1;
        if (NV > 2) o2[n] = s2;
        if (NV > 3) o3[n] = s3;
    }
}

// ---------------- L2 scalar aggregation (gather, no atomics) ----------------
__global__ void k_s2_p(const int* __restrict__ rp1, const int* __restrict__ rp3,
                       const int* __restrict__ srcs,
                       const float* __restrict__ as1, const float* __restrict__ ad1,
                       const float* __restrict__ hw1,
                       const float* __restrict__ as3, const float* __restrict__ ad3,
                       const float* __restrict__ hw3,
                       const float* __restrict__ cb, float* __restrict__ o, int N) {
    int n = (blockIdx.x * blockDim.x + threadIdx.x) >> 5;
    int lane = threadIdx.x & 31;
    if (n >= N) return;
    float n1 = 0.f, d1 = 0.f, n3 = 0.f, d3 = 0.f;
    float a1 = ad1[n], a3 = ad3[n];
    int b = rp1[n], e = rp1[n + 1];
    for (int j = b + lane; j < e; j += 32) {
        int s = __ldg(srcs + j);
        float x = __ldg(as1 + s) + a1;
        x = (x >= 0.f) ? x : 0.2f * x;
        float ex = __expf(x);
        d1 += ex; n1 += ex * __ldg(hw1 + s);
    }
    b = rp3[n]; e = rp3[n + 1];
    for (int j = b + lane; j < e; j += 32) {
        int s = __ldg(srcs + j);
        float x = __ldg(as3 + s) + a3;
        x = (x >= 0.f) ? x : 0.2f * x;
        float ex = __expf(x);
        d3 += ex; n3 += ex * __ldg(hw3 + s);
    }
    n1 = warp_sum(n1); d1 = warp_sum(d1);
    n3 = warp_sum(n3); d3 = warp_sum(d3);
    if (lane == 0)
        o[n] = ((d1 > 0.f) ? n1 / d1 : 0.f) + ((d3 > 0.f) ? n3 / d3 : 0.f) + cb[0];
}

__global__ void k_s2_m(const int* __restrict__ rp, const int* __restrict__ srcs,
                       const float* __restrict__ as_, const float* __restrict__ ad_,
                       const float* __restrict__ hw,
                       const float* __restrict__ cb, float* __restrict__ o, int N) {
    int n = (blockIdx.x * blockDim.x + threadIdx.x) >> 5;
    int lane = threadIdx.x & 31;
    if (n >= N) return;
    float nm = 0.f, dn = 0.f;
    float a = ad_[n];
    int b = rp[n], e = rp[n + 1];
    for (int j = b + lane; j < e; j += 32) {
        int s = __ldg(srcs + j);
        float x = __ldg(as_ + s) + a;
        x = (x >= 0.f) ? x : 0.2f * x;
        float ex = __expf(x);
        dn += ex; nm += ex * __ldg(hw + s);
    }
    nm = warp_sum(nm); dn = warp_sum(dn);
    if (lane == 0) o[n] = ((dn > 0.f) ? nm / dn : 0.f) + cb[1];
}

__global__ void k_final(const int* __restrict__ row, const int* __restrict__ col,
                        const float* __restrict__ sp, const float* __restrict__ sm,
                        const float* __restrict__ lb, float* __restrict__ out, int n) {
    int j = blockIdx.x * blockDim.x + threadIdx.x;
    if (j < n) out[j] = sp[row[j]] + sm[col[j]] + lb[0];
}

// ---------------- host ----------------
static inline int cdiv(int a, int b) { return (a + b - 1) / b; }

extern "C" void kernel_launch(void* const* d_in, const int* in_sizes, int n_in,
                              void* d_out, int out_size) {
    const int* src_pd = (const int*)d_in[0];
    const int* dst_pd = (const int*)d_in[1];
    const int* src_dp = (const int*)d_in[2];
    const int* dst_dp = (const int*)d_in[3];
    const int* src_pm = (const int*)d_in[4];
    const int* dst_pm = (const int*)d_in[5];
    const int* src_mp = (const int*)d_in[6];
    const int* dst_mp = (const int*)d_in[7];
    const int* row    = (const int*)d_in[8];
    const int* col    = (const int*)d_in[9];
    const float* x_p  = (const float*)d_in[10];
    const float* x_d  = (const float*)d_in[11];
    const float* x_m  = (const float*)d_in[12];
    const float* W1s  = (const float*)d_in[13];
    const float* W1d  = (const float*)d_in[14];
    const float* a1s  = (const float*)d_in[15];
    const float* a1d  = (const float*)d_in[16];
    const float* b1   = (const float*)d_in[17];
    const float* W2s  = (const float*)d_in[18];
    const float* W2d  = (const float*)d_in[19];
    const float* a2s  = (const float*)d_in[20];
    const float* a2d  = (const float*)d_in[21];
    const float* b2   = (const float*)d_in[22];
    const float* linw = (const float*)d_in[23];
    const float* linb = (const float*)d_in[24];
    float* out = (float*)d_out;

    int *cnt, *rowptr, *wp, *bsum, *bexcl, *srcs;
    float *vec, *u, *cb, *sp, *sm;
    __half *xh, *wt, *hspc, *hsd, *hsm;
    float *as0, *ad1, *as2, *ad3, *ad0, *as1, *ad2, *as3;
    float *as1b, *hwd, *ad2b, *as3b, *hwm, *ad1b, *as2b, *ad3b, *hwp;
    cudaGetSymbolAddress((void**)&cnt,    g_cnt);
    cudaGetSymbolAddress((void**)&rowptr, g_rowptr);
    cudaGetSymbolAddress((void**)&wp,     g_wp);
    cudaGetSymbolAddress((void**)&bsum,   g_bsum);
    cudaGetSymbolAddress((void**)&bexcl,  g_bexcl);
    cudaGetSymbolAddress((void**)&srcs,   g_srcs);
    cudaGetSymbolAddress((void**)&xh,     g_xh);
    cudaGetSymbolAddress((void**)&wt,     g_wt);
    cudaGetSymbolAddress((void**)&hspc,   g_hspc);
    cudaGetSymbolAddress((void**)&hsd,    g_hsd);
    cudaGetSymbolAddress((void**)&hsm,    g_hsm);
    cudaGetSymbolAddress((void**)&vec,    g_vec);
    cudaGetSymbolAddress((void**)&u,      g_u);
    cudaGetSymbolAddress((void**)&cb,     g_cb);
    cudaGetSymbolAddress((void**)&sp,     g_sp);
    cudaGetSymbolAddress((void**)&sm,     g_sm);
    cudaGetSymbolAddress((void**)&as0,    g_as0);
    cudaGetSymbolAddress((void**)&ad1,    g_ad1);
    cudaGetSymbolAddress((void**)&as2,    g_as2);
    cudaGetSymbolAddress((void**)&ad3,    g_ad3);
    cudaGetSymbolAddress((void**)&ad0,    g_ad0);
    cudaGetSymbolAddress((void**)&as1,    g_as1);
    cudaGetSymbolAddress((void**)&ad2,    g_ad2);
    cudaGetSymbolAddress((void**)&as3,    g_as3);
    cudaGetSymbolAddress((void**)&as1b,   g_as1b);
    cudaGetSymbolAddress((void**)&hwd,    g_hwd);
    cudaGetSymbolAddress((void**)&ad2b,   g_ad2b);
    cudaGetSymbolAddress((void**)&as3b,   g_as3b);
    cudaGetSymbolAddress((void**)&hwm,    g_hwm);
    cudaGetSymbolAddress((void**)&ad1b,   g_ad1b);
    cudaGetSymbolAddress((void**)&as2b,   g_as2b);
    cudaGetSymbolAddress((void**)&ad3b,   g_ad3b);
    cudaGetSymbolAddress((void**)&hwp,    g_hwp);

    __half* xh_p = xh;
    __half* xh_d = xh + (size_t)NP * HD;
    __half* xh_m = xh + (size_t)(NP + ND) * HD;
    __half* hs0 = hspc;
    __half* hs2 = hspc + (size_t)NP * HD;
    __half* wt0 = wt;
    __half* wt1 = wt + 1 * HD * HD;
    __half* wt2 = wt + 2 * HD * HD;
    __half* wt3 = wt + 3 * HD * HD;

    #define VEC(L, ET, W) (vec + (size_t)(((L) * 4 + (ET)) * 2 + (W)) * HD)

    // Streams/events: HOST objects created ONCE on the first call (before the
    // harness's pre-capture memory baseline) and reused.
    static cudaStream_t sA = nullptr, sB = nullptr, sC = nullptr;
    static cudaEvent_t evRoot = nullptr, evA = nullptr, evMD = nullptr;
    static cudaEvent_t evB = nullptr, evG0 = nullptr, evD = nullptr;
    if (sA == nullptr) {
        cudaStreamCreateWithFlags(&sA, cudaStreamNonBlocking);
        cudaStreamCreateWithFlags(&sB, cudaStreamNonBlocking);
        cudaStreamCreateWithFlags(&sC, cudaStreamNonBlocking);
        cudaEventCreateWithFlags(&evRoot, cudaEventDisableTiming);
        cudaEventCreateWithFlags(&evA, cudaEventDisableTiming);
        cudaEventCreateWithFlags(&evMD, cudaEventDisableTiming);
        cudaEventCreateWithFlags(&evB, cudaEventDisableTiming);
        cudaEventCreateWithFlags(&evG0, cudaEventDisableTiming);
        cudaEventCreateWithFlags(&evD, cudaEventDisableTiming);
        k_consts<<<1, 64, 0, sA>>>(b2, linw, cb);
        k_consts<<<1, 64, 0, sB>>>(b2, linw, cb);
        k_consts<<<1, 64, 0, sC>>>(b2, linw, cb);
        cudaStreamSynchronize(sA);
        cudaStreamSynchronize(sB);
        cudaStreamSynchronize(sC);
    }

    cudaEventRecord(evRoot, 0);
    cudaStreamWaitEvent(sA, evRoot, 0);
    cudaStreamWaitEvent(sB, evRoot, 0);
    cudaStreamWaitEvent(sC, evRoot, 0);

    // ===== stream sA: CSR build (single fused chain) =====
    cudaMemsetAsync(cnt, 0, TOT * sizeof(int), sA);
    k_hist<<<cdiv(4 * EE, 256), 256, 0, sA>>>(dst_pd, dst_dp, dst_pm, dst_mp, cnt);
    k_scan1<<<NBLK, 1024, 0, sA>>>(cnt, rowptr, bsum);
    k_scan2<<<1, 256, 0, sA>>>(bsum, bexcl);
    k_scan3<<<NBLK, 1024, 0, sA>>>(rowptr, bexcl, wp);
    k_fill<<<cdiv(4 * EE, 256), 256, 0, sA>>>(src_pd, dst_pd, src_dp, dst_dp,
                                              src_pm, dst_pm, src_mp, dst_mp, wp, srcs);
    cudaEventRecord(evA, sA);

    const int* rp_pd = rowptr + SEG_PD;
    const int* rp_dp = rowptr + SEG_DP;
    const int* rp_pm = rowptr + SEG_PM;
    const int* rp_mp = rowptr + SEG_MP;

    // ===== stream sC: fused prep + L1 attention scalars -> evMD, then disease agg =====
    k_prep<<<cdiv(2434, 256), 256, 0, sC>>>(W1s, a1s, W1d, a1d, W2s, a2s, W2d, a2d,
                                            linw, b2, vec, u, cb);
    k_multi_dot4<<<cdiv(NP * 32, 256), 256, 0, sC>>>((const float4*)x_p, NP,
        (const float4*)VEC(0,0,0), (const float4*)VEC(0,1,1),
        (const float4*)VEC(0,2,0), (const float4*)VEC(0,3,1), as0, ad1, as2, ad3);
    k_multi_dot4<<<cdiv(ND * 32, 256), 256, 0, sC>>>((const float4*)x_d, ND,
        (const float4*)VEC(0,0,1), (const float4*)VEC(0,1,0),
        nullptr, nullptr, ad0, as1, nullptr, nullptr);
    k_multi_dot4<<<cdiv(NM * 32, 256), 256, 0, sC>>>((const float4*)x_m, NM,
        (const float4*)VEC(0,2,1), (const float4*)VEC(0,3,0),
        nullptr, nullptr, ad2, as3, nullptr, nullptr);
    cudaEventRecord(evMD, sC);

    // ===== main stream: self-contained patient GEMM chain =====
    k_cvtW<<<cdiv(HD * HD, 256), 256>>>(W1s + 0 * HD * HD, wt0);
    k_cvtW<<<cdiv(HD * HD, 256), 256>>>(W1s + 2 * HD * HD, wt2);
    k_cvt<<<cdiv(NP * HD / 4, 256), 256>>>((const float4*)x_p, (uint2*)xh_p, NP * HD / 4);
    {
        dim3 g1(cdiv(NP, 128), 2);
        k_gemm_f16<<<g1, 256>>>(xh_p, wt0, hs0, NP, HD);
    }
    cudaEventRecord(evG0, 0);
    {
        dim3 g1(cdiv(NP, 128), 2);
        k_gemm_f16<<<g1, 256>>>(xh_p, wt2, hs2, NP, HD);
    }

    // ===== stream sB: small-GEMM chain + patient agg (critical consumer) =====
    k_cvtW<<<cdiv(HD * HD, 256), 256, 0, sB>>>(W1s + 1 * HD * HD, wt1);
    k_cvtW<<<cdiv(HD * HD, 256), 256, 0, sB>>>(W1s + 3 * HD * HD, wt3);
    k_cvt<<<cdiv(ND * HD / 4, 256), 256, 0, sB>>>((const float4*)x_d, (uint2*)xh_d, ND * HD / 4);
    k_cvt<<<cdiv(NM * HD / 4, 256), 256, 0, sB>>>((const float4*)x_m, (uint2*)xh_m, NM * HD / 4);
    {
        dim3 g2(cdiv(ND, 128), 2);
        k_gemm_f16<<<g2, 256, 0, sB>>>(xh_d, wt1, hsd, ND, HD);
        dim3 g3(cdiv(NM, 128), 2);
        k_gemm_f16<<<g3, 256, 0, sB>>>(xh_m, wt3, hsm, NM, HD);
    }
    cudaStreamWaitEvent(sB, evA, 0);
    cudaStreamWaitEvent(sB, evMD, 0);
    k_agg_dot<4, true><<<cdiv(NP * 32, 256), 256, 0, sB>>>(
        rp_dp, rp_mp, srcs, as1, ad1, as3, ad3,
        (const uint4*)hsd, 16, 0, (const uint4*)hsm, 16, 0,
        b1 + 1 * HD, b1 + 3 * HD,
        VEC(1,1,1), VEC(1,2,0), VEC(1,3,1), u + 1 * HD,
        ad1b, as2b, ad3b, hwp, NP);
    cudaEventRecord(evB, sB);

    // ===== stream sC: disease agg (needs GEMM0 + CSR + multi_dots) =====
    cudaStreamWaitEvent(sC, evG0, 0);
    cudaStreamWaitEvent(sC, evA, 0);
    k_agg_dot<2, false><<<cdiv(ND * 32, 256), 256, 0, sC>>>(
        rp_pd, nullptr, srcs, as0, ad0, nullptr, nullptr,
        (const uint4*)hs0, 16, 0, nullptr, 0, 0,
        b1 + 0 * HD, nullptr,
        VEC(1,1,0), u + 0 * HD, nullptr, nullptr,
        as1b, hwd, nullptr, nullptr, ND);
    cudaEventRecord(evD, sC);

    // ===== main: medicine agg (needs GEMM2 + CSR + multi_dots) =====
    cudaStreamWaitEvent(0, evA, 0);
    cudaStreamWaitEvent(0, evMD, 0);
    k_agg_dot<3, false><<<cdiv(NM * 32, 256), 256>>>(
        rp_pm, nullptr, srcs, as2, ad2, nullptr, nullptr,
        (const uint4*)hs2, 16, 0, nullptr, 0, 0,
        b1 + 2 * HD, nullptr,
        VEC(1,2,1), VEC(1,3,0), u + 2 * HD, nullptr,
        ad2b, as3b, hwm, nullptr, NM);

    // ===== join: L2 scalar aggregation + head =====
    cudaStreamWaitEvent(0, evB, 0);
    cudaStreamWaitEvent(0, evD, 0);
    k_s2_p<<<cdiv(NP * 32, 256), 256>>>(rp_dp, rp_mp, srcs,
        as1b, ad1b, hwd, as3b, ad3b, hwm, cb, sp, NP);
    k_s2_m<<<cdiv(NM * 32, 256), 256>>>(rp_pm, srcs, as2b, ad2b, hwp, cb, sm, NM);
    k_final<<<cdiv(ELN, 256), 256>>>(row, col, sp, sm, linb, out, ELN);
    #undef VEC
}

// round 16
// speedup vs baseline: 1.1058x; 1.0502x over previous
#include <cuda_runtime.h>
#include <cuda_fp16.h>
#include <cuda_bf16.h>

#define NP 100000
#define ND 30000
#define NM 20000
#define EE 600000
#define ELN 200000
#define HD 128
#define CD 64

// CSR segment layout over concatenated dst spaces:
// [pd: ND rows][dp: NP rows][pm: NM rows][mp: NP rows]
#define SEG_PD 0
#define SEG_DP (ND)
#define SEG_PM (ND + NP)
#define SEG_MP (ND + NP + NM)
#define TOT    (ND + NP + NM + NP)          // 250000
#define NBLK   ((TOT + 1023) / 1024)        // 245

// ---------------- static device scratch ----------------
__device__ __align__(256) int g_cnt[TOT];
__device__ __align__(256) int g_rowptr[TOT + 1];
__device__ __align__(256) int g_wp[TOT];
__device__ __align__(256) int g_bsum[NBLK];
__device__ __align__(256) int g_bexcl[NBLK];
__device__ __align__(256) int g_srcs[4 * EE];

__device__ __align__(256) __half g_xh[(NP + ND + NM) * HD];  // fp16 embeddings
__device__ __align__(256) __half g_wt[4 * HD * HD];          // fp16 transposed W1s[et]
__device__ __align__(256) __half g_hspc[NP * 256];  // [hs0: x_p@W1s0][hs2: x_p@W1s2]
__device__ __align__(256) __half g_hsd [ND * HD];
__device__ __align__(256) __half g_hsm [NM * HD];
__device__ __align__(256) float g_vec[16 * HD];
__device__ __align__(256) float g_u[3 * HD];
__device__ __align__(256) float g_cb[2];
// L1 attention scalars (from raw embeddings)
__device__ __align__(256) float g_as0[NP], g_ad1[NP], g_as2[NP], g_ad3[NP];
__device__ __align__(256) float g_ad0[ND], g_as1[ND];
__device__ __align__(256) float g_ad2[NM], g_as3[NM];
// L2 attention scalars + h.u dots (from fused agg)
__device__ __align__(256) float g_as1b[ND], g_hwd[ND];
__device__ __align__(256) float g_ad2b[NM], g_as3b[NM], g_hwm[NM];
__device__ __align__(256) float g_ad1b[NP], g_as2b[NP], g_ad3b[NP], g_hwp[NP];
__device__ __align__(256) float g_sp[NP], g_sm[NM];

// ---------------- helpers ----------------
__device__ __forceinline__ float warp_sum(float v) {
    #pragma unroll
    for (int o = 16; o; o >>= 1) v += __shfl_down_sync(0xFFFFFFFFu, v, o);
    return v;
}
__device__ __forceinline__ float sub8_sum(float v) {
    v += __shfl_down_sync(0xFFFFFFFFu, v, 4, 8);
    v += __shfl_down_sync(0xFFFFFFFFu, v, 2, 8);
    v += __shfl_down_sync(0xFFFFFFFFu, v, 1, 8);
    return v;
}
__device__ __forceinline__ float dot4(float4 a, float4 b) {
    return a.x * b.x + a.y * b.y + a.z * b.z + a.w * b.w;
}

// ---------------- prep kernels ----------------
__global__ void k_cvt(const float4* __restrict__ x, uint2* __restrict__ o, int n4) {
    int i = blockIdx.x * blockDim.x + threadIdx.x;
    if (i >= n4) return;
    float4 v = x[i];
    __half2 lo = __floats2half2_rn(v.x, v.y);
    __half2 hi = __floats2half2_rn(v.z, v.w);
    uint2 r;
    r.x = *(unsigned*)&lo;
    r.y = *(unsigned*)&hi;
    o[i] = r;
}

// WT[n][k] = fp16(W[k][n]);  W: [128][128] fp32 row-major (k-major)
__global__ void k_cvtW(const float* __restrict__ W, __half* __restrict__ WT) {
    int i = blockIdx.x * blockDim.x + threadIdx.x;   // 16384
    int n = i >> 7, k = i & 127;
    WT[(size_t)n * HD + k] = __float2half_rn(W[(size_t)k * HD + n]);
}

// fused: L1 vecs [0,1024) | L2 vecs [1024,2048) | uvecs [2048,2432) | cb [2432,2434)
__global__ void k_prep(const float* __restrict__ W1s, const float* __restrict__ a1s,
                       const float* __restrict__ W1d, const float* __restrict__ a1d,
                       const float* __restrict__ W2s, const float* __restrict__ a2s,
                       const float* __restrict__ W2d, const float* __restrict__ a2d,
                       const float* __restrict__ linw, const float* __restrict__ b2,
                       float* __restrict__ vec, float* __restrict__ u,
                       float* __restrict__ cb) {
    int idx = blockIdx.x * blockDim.x + threadIdx.x;
    if (idx < 1024) {
        int k = idx % HD, w = (idx / HD) & 1, et = idx / (2 * HD);
        const float* W = w ? W1d : W1s;
        const float* a = w ? a1d : a1s;
        const float* Wrow = W + (size_t)et * HD * HD + (size_t)k * HD;
        const float* av = a + (size_t)et * HD;
        float s = 0.f;
        for (int j = 0; j < HD; j++) s += Wrow[j] * av[j];
        vec[idx] = s;
    } else if (idx < 2048) {
        int li = idx - 1024;
        int k = li % HD, w = (li / HD) & 1, et = li / (2 * HD);
        const float* W = w ? W2d : W2s;
        const float* a = w ? a2d : a2s;
        const float* Wrow = W + (size_t)et * HD * CD + (size_t)k * CD;
        const float* av = a + (size_t)et * CD;
        float s = 0.f;
        for (int j = 0; j < CD; j++) s += Wrow[j] * av[j];
        vec[8 * HD + li] = s;
    } else if (idx < 2432) {
        int li = idx - 2048;
        int e = li / HD, k = li % HD;
        const float* W = W2s + (size_t)(e + 1) * HD * CD + (size_t)k * CD;
        const float* w = linw + ((e == 1) ? CD : 0);
        float s = 0.f;
        for (int j = 0; j < CD; j++) s += W[j] * w[j];
        u[li] = s;
    } else if (idx == 2432) {
        float s = 0.f;
        for (int j = 0; j < CD; j++) s += (b2[CD + j] + b2[3 * CD + j]) * linw[j];
        cb[0] = s;
    } else if (idx == 2433) {
        float s = 0.f;
        for (int j = 0; j < CD; j++) s += b2[2 * CD + j] * linw[CD + j];
        cb[1] = s;
    }
}

__global__ void k_consts(const float* __restrict__ b2, const float* __restrict__ linw,
                         float* __restrict__ cb) {
    int lane = threadIdx.x & 31, w = threadIdx.x >> 5;
    float s;
    if (w == 0) {
        s = (b2[1 * CD + lane] + b2[3 * CD + lane]) * linw[lane]
          + (b2[1 * CD + lane + 32] + b2[3 * CD + lane + 32]) * linw[lane + 32];
    } else {
        s = b2[2 * CD + lane] * linw[CD + lane]
          + b2[2 * CD + lane + 32] * linw[CD + lane + 32];
    }
    s = warp_sum(s);
    if (lane == 0) cb[w] = s;
}

// DIM=128: one float4 per lane per operand
__global__ void k_multi_dot4(const float4* __restrict__ x, int N,
                             const float4* __restrict__ v0, const float4* __restrict__ v1,
                             const float4* __restrict__ v2, const float4* __restrict__ v3,
                             float* __restrict__ o0, float* __restrict__ o1,
                             float* __restrict__ o2, float* __restrict__ o3) {
    int warp = (blockIdx.x * blockDim.x + threadIdx.x) >> 5;
    int lane = threadIdx.x & 31;
    if (warp >= N) return;
    float4 xv = __ldg(x + (size_t)warp * 32 + lane);
    float s0 = dot4(xv, __ldg(v0 + lane));
    float s1 = v1 ? dot4(xv, __ldg(v1 + lane)) : 0.f;
    float s2 = v2 ? dot4(xv, __ldg(v2 + lane)) : 0.f;
    float s3 = v3 ? dot4(xv, __ldg(v3 + lane)) : 0.f;
    s0 = warp_sum(s0);
    if (v1) s1 = warp_sum(s1);
    if (v2) s2 = warp_sum(s2);
    if (v3) s3 = warp_sum(s3);
    if (lane == 0) {
        o0[warp] = s0;
        if (o1) o1[warp] = s1;
        if (o2) o2[warp] = s2;
        if (o3) o3[warp] = s3;
    }
}

// ---------------- CSR build ----------------
__global__ void k_hist(const int* __restrict__ d_pd, const int* __restrict__ d_dp,
                       const int* __restrict__ d_pm, const int* __restrict__ d_mp,
                       int* __restrict__ cnt) {
    int idx = blockIdx.x * blockDim.x + threadIdx.x;
    if (idx >= 4 * EE) return;
    int r = idx / EE, e = idx - r * EE;
    int d, base;
    if (r == 0)      { d = d_pd[e]; base = SEG_PD; }
    else if (r == 1) { d = d_dp[e]; base = SEG_DP; }
    else if (r == 2) { d = d_pm[e]; base = SEG_PM; }
    else             { d = d_mp[e]; base = SEG_MP; }
    atomicAdd(cnt + base + d, 1);
}

__global__ void k_scan1(const int* __restrict__ cnt, int* __restrict__ rp,
                        int* __restrict__ bsum) {
    __shared__ int sh[1024];
    int t = threadIdx.x;
    int i = blockIdx.x * 1024 + t;
    int v = (i < TOT) ? cnt[i] : 0;
    sh[t] = v;
    __syncthreads();
    for (int o = 1; o < 1024; o <<= 1) {
        int x = (t >= o) ? sh[t - o] : 0;
        __syncthreads();
        sh[t] += x;
        __syncthreads();
    }
    if (i < TOT) rp[i] = sh[t] - v;
    if (t == 1023) bsum[blockIdx.x] = sh[1023];
}

__global__ void k_scan2(const int* __restrict__ bsum, int* __restrict__ bexcl) {
    __shared__ int sh[256];
    int t = threadIdx.x;
    int v = (t < NBLK) ? bsum[t] : 0;
    sh[t] = v;
    __syncthreads();
    for (int o = 1; o < 256; o <<= 1) {
        int x = (t >= o) ? sh[t - o] : 0;
        __syncthreads();
        sh[t] += x;
        __syncthreads();
    }
    if (t < NBLK) bexcl[t] = sh[t] - v;
}

__global__ void k_scan3(int* __restrict__ rp, const int* __restrict__ bexcl,
                        int* __restrict__ wp) {
    int i = blockIdx.x * 1024 + threadIdx.x;
    if (i < TOT) {
        int v = rp[i] + bexcl[blockIdx.x];
        rp[i] = v;
        wp[i] = v;
    }
    if (i == 0) rp[TOT] = 4 * EE;
}

__global__ void k_fill(const int* __restrict__ s_pd, const int* __restrict__ d_pd,
                       const int* __restrict__ s_dp, const int* __restrict__ d_dp,
                       const int* __restrict__ s_pm, const int* __restrict__ d_pm,
                       const int* __restrict__ s_mp, const int* __restrict__ d_mp,
                       int* __restrict__ wp, int* __restrict__ srcs) {
    int idx = blockIdx.x * blockDim.x + threadIdx.x;
    if (idx >= 4 * EE) return;
    int r = idx / EE, e = idx - r * EE;
    int d, s, base;
    if (r == 0)      { d = d_pd[e]; s = s_pd[e]; base = SEG_PD; }
    else if (r == 1) { d = d_dp[e]; s = s_dp[e]; base = SEG_DP; }
    else if (r == 2) { d = d_pm[e]; s = s_pm[e]; base = SEG_PM; }
    else             { d = d_mp[e]; s = s_mp[e]; base = SEG_MP; }
    int pos = atomicAdd(wp + base + d, 1);
    srcs[pos] = s;
}

// ---------------- fp16 GEMM: C[M,64/block] = A[M,128] @ WT^T, mma m16n8k16 ----------------
__device__ __forceinline__ void mma_f16(float* d, const unsigned* a, const unsigned* b) {
    asm volatile(
        "mma.sync.aligned.m16n8k16.row.col.f32.f16.f16.f32 "
        "{%0,%1,%2,%3}, {%4,%5,%6,%7}, {%8,%9}, {%0,%1,%2,%3};"
        : "+f"(d[0]), "+f"(d[1]), "+f"(d[2]), "+f"(d[3])
        : "r"(a[0]), "r"(a[1]), "r"(a[2]), "r"(a[3]), "r"(b[0]), "r"(b[1]));
}

__global__ __launch_bounds__(256) void k_gemm_f16(const __half* __restrict__ A,
                                                  const __half* __restrict__ WT,
                                                  __half* __restrict__ C,
                                                  int M, int ldc) {
    __shared__ __half As[2][128][40];    // u32 bank (20r + t) % 32: conflict-free
    __shared__ __half Bsn[2][64][40];    // [n][k]
    int tid = threadIdx.x;
    int lane = tid & 31, warp = tid >> 5;
    int gid = lane >> 2, tig = lane & 3;
    int wm = warp & 3, wn = warp >> 2;
    int m0 = blockIdx.x * 128, n0 = blockIdx.y * 64;

    float acc[2][4][4];
    #pragma unroll
    for (int i = 0; i < 2; i++)
        #pragma unroll
        for (int j = 0; j < 4; j++)
            #pragma unroll
            for (int l = 0; l < 4; l++) acc[i][j][l] = 0.f;

    auto load_stage = [&](int kb, int buf) {
        #pragma unroll
        for (int i = 0; i < 2; i++) {
            int f = i * 256 + tid;          // 0..511
            int m = f >> 2;
            int c8 = (f & 3) * 8;
            const __half* src = A + (size_t)(m0 + m) * 128 + kb * 32 + c8;
            unsigned ds = (unsigned)__cvta_generic_to_shared(&As[buf][m][c8]);
            int p = (m0 + m < M) ? 16 : 0;
            asm volatile("cp.async.cg.shared.global [%0], [%1], 16, %2;"
                         :: "r"(ds), "l"(src), "r"(p));
        }
        {
            int n = tid >> 2;                // 0..63
            int c8 = (tid & 3) * 8;
            const __half* src = WT + (size_t)(n0 + n) * 128 + kb * 32 + c8;
            unsigned ds = (unsigned)__cvta_generic_to_shared(&Bsn[buf][n][c8]);
            asm volatile("cp.async.cg.shared.global [%0], [%1], 16, 16;"
                         :: "r"(ds), "l"(src));
        }
        asm volatile("cp.async.commit_group;");
    };

    load_stage(0, 0);

    for (int kb = 0; kb < 4; kb++) {
        if (kb < 3) {
            load_stage(kb + 1, (kb + 1) & 1);
            asm volatile("cp.async.wait_group 1;");
        } else {
            asm volatile("cp.async.wait_group 0;");
        }
        __syncthreads();
        int buf = kb & 1;
        #pragma unroll
        for (int ks = 0; ks < 2; ks++) {
            int kk = ks * 16;
            unsigned a[2][4], b[4][2];
            #pragma unroll
            for (int ms = 0; ms < 2; ms++) {
                int r = wm * 32 + ms * 16 + gid;
                a[ms][0] = *(const unsigned*)&As[buf][r][kk + tig * 2];
                a[ms][1] = *(const unsigned*)&As[buf][r + 8][kk + tig * 2];
                a[ms][2] = *(const unsigned*)&As[buf][r][kk + 8 + tig * 2];
                a[ms][3] = *(const unsigned*)&As[buf][r + 8][kk + 8 + tig * 2];
            }
            #pragma unroll
            for (int ns = 0; ns < 4; ns++) {
                int c = wn * 32 + ns * 8 + gid;
                b[ns][0] = *(const unsigned*)&Bsn[buf][c][kk + tig * 2];
                b[ns][1] = *(const unsigned*)&Bsn[buf][c][kk + 8 + tig * 2];
            }
            #pragma unroll
            for (int ms = 0; ms < 2; ms++)
                #pragma unroll
                for (int ns = 0; ns < 4; ns++) mma_f16(acc[ms][ns], a[ms], b[ns]);
        }
        __syncthreads();
    }

    #pragma unroll
    for (int ms = 0; ms < 2; ms++) {
        int r = m0 + wm * 32 + ms * 16 + gid;
        #pragma unroll
        for (int ns = 0; ns < 4; ns++) {
            int c = n0 + wn * 32 + ns * 8 + 2 * tig;
            if (r < M)
                *(__half2*)(C + (size_t)r * ldc + c) = __floats2half2_rn(acc[ms][ns][0], acc[ms][ns][1]);
            if (r + 8 < M)
                *(__half2*)(C + (size_t)(r + 8) * ldc + c) = __floats2half2_rn(acc[ms][ns][2], acc[ms][ns][3]);
        }
    }
}

// ---------------- agg segment: shuffle-broadcast indices + 2-stage pipeline ----------------
__device__ __forceinline__ void agg_segment(
    int b, int e, const int* __restrict__ srcs,
    const float* __restrict__ as_, float adv,
    const uint4* __restrict__ hs, int srow, int soff,
    int lane, int half, int l16, float* acc, float& den)
{
    for (int c0 = b; c0 < e; c0 += 32) {
        int idx = c0 + lane;
        int sv = (idx < e) ? __ldg(srcs + idx) : 0;   // coalesced index chunk
        int cnt = min(32, e - c0);
        int s_c = __shfl_sync(0xFFFFFFFFu, sv, min(half, cnt - 1));
        float a_c = __ldg(as_ + s_c);
        uint4 h_c = __ldg(hs + (size_t)s_c * srow + soff + l16);
        for (int t2 = 0; t2 < cnt; t2 += 2) {
            int t2n = t2 + 2;
            int sh = (t2n < cnt) ? min(t2n + half, cnt - 1) : 0;
            int s_n = __shfl_sync(0xFFFFFFFFu, sv, sh);
            float a_n = __ldg(as_ + s_n);
            uint4 h_n = __ldg(hs + (size_t)s_n * srow + soff + l16);
            float x = a_c + adv;
            x = (x >= 0.f) ? x : 0.2f * x;
            float ex = (t2 + half < cnt) ? __expf(x) : 0.f;
            den += ex;
            float2 f0 = __half22float2(*(__half2*)&h_c.x);
            float2 f1 = __half22float2(*(__half2*)&h_c.y);
            float2 f2 = __half22float2(*(__half2*)&h_c.z);
            float2 f3 = __half22float2(*(__half2*)&h_c.w);
            acc[0] += ex * f0.x; acc[1] += ex * f0.y;
            acc[2] += ex * f1.x; acc[3] += ex * f1.y;
            acc[4] += ex * f2.x; acc[5] += ex * f2.y;
            acc[6] += ex * f3.x; acc[7] += ex * f3.y;
            s_c = s_n; a_c = a_n; h_c = h_n;
        }
    }
}

// ---------------- fused L1 aggregation: gather + softmax + relu + dots ----------------
template<int NV, bool DUAL>
__global__ __launch_bounds__(256) void k_agg_dot(
    const int* __restrict__ rpA, const int* __restrict__ rpB,
    const int* __restrict__ srcs,
    const float* __restrict__ asA, const float* __restrict__ adA,
    const float* __restrict__ asB, const float* __restrict__ adB,
    const uint4* __restrict__ hsA, int srowA, int soffA,
    const uint4* __restrict__ hsB, int srowB, int soffB,
    const float* __restrict__ ba, const float* __restrict__ bb,
    const float* __restrict__ v0, const float* __restrict__ v1,
    const float* __restrict__ v2, const float* __restrict__ v3,
    float* __restrict__ o0, float* __restrict__ o1,
    float* __restrict__ o2, float* __restrict__ o3, int N)
{
    int n = (blockIdx.x * blockDim.x + threadIdx.x) >> 5;
    int lane = threadIdx.x & 31;
    if (n >= N) return;
    int half = lane >> 4, l16 = lane & 15;

    float acc[8], den = 0.f;
    #pragma unroll
    for (int i = 0; i < 8; i++) acc[i] = 0.f;
    agg_segment(rpA[n], rpA[n + 1], srcs, asA, adA[n], hsA, srowA, soffA,
                lane, half, l16, acc, den);

    float accB[8], denB = 0.f;
    if (DUAL) {
        #pragma unroll
        for (int i = 0; i < 8; i++) accB[i] = 0.f;
        agg_segment(rpB[n], rpB[n + 1], srcs, asB, adB[n], hsB, srowB, soffB,
                    lane, half, l16, accB, denB);
    }

    #pragma unroll
    for (int i = 0; i < 8; i++) acc[i] += __shfl_down_sync(0xFFFFFFFFu, acc[i], 16);
    den += __shfl_down_sync(0xFFFFFFFFu, den, 16);
    if (DUAL) {
        #pragma unroll
        for (int i = 0; i < 8; i++) accB[i] += __shfl_down_sync(0xFFFFFFFFu, accB[i], 16);
        denB += __shfl_down_sync(0xFFFFFFFFu, denB, 16);
    }

    float r = (den > 0.f) ? 1.f / den : 0.f;
    float4 bv0 = __ldg((const float4*)ba + l16 * 2);
    float4 bv1 = __ldg((const float4*)ba + l16 * 2 + 1);
    float h[8];
    h[0] = acc[0] * r + bv0.x; h[1] = acc[1] * r + bv0.y;
    h[2] = acc[2] * r + bv0.z; h[3] = acc[3] * r + bv0.w;
    h[4] = acc[4] * r + bv1.x; h[5] = acc[5] * r + bv1.y;
    h[6] = acc[6] * r + bv1.z; h[7] = acc[7] * r + bv1.w;
    if (DUAL) {
        float rB = (denB > 0.f) ? 1.f / denB : 0.f;
        float4 c0 = __ldg((const float4*)bb + l16 * 2);
        float4 c1 = __ldg((const float4*)bb + l16 * 2 + 1);
        h[0] += accB[0] * rB + c0.x; h[1] += accB[1] * rB + c0.y;
        h[2] += accB[2] * rB + c0.z; h[3] += accB[3] * rB + c0.w;
        h[4] += accB[4] * rB + c1.x; h[5] += accB[5] * rB + c1.y;
        h[6] += accB[6] * rB + c1.z; h[7] += accB[7] * rB + c1.w;
    }
    #pragma unroll
    for (int i = 0; i < 8; i++) h[i] = fmaxf(h[i], 0.f);

    float s0 = 0.f, s1 = 0.f, s2 = 0.f, s3 = 0.f;
    {
        float4 a = __ldg((const float4*)v0 + l16 * 2);
        float4 b = __ldg((const float4*)v0 + l16 * 2 + 1);
        s0 = h[0]*a.x + h[1]*a.y + h[2]*a.z + h[3]*a.w
           + h[4]*b.x + h[5]*b.y + h[6]*b.z + h[7]*b.w;
    }
    if (NV > 1) {
        float4 a = __ldg((const float4*)v1 + l16 * 2);
        float4 b = __ldg((const float4*)v1 + l16 * 2 + 1);
        s1 = h[0]*a.x + h[1]*a.y + h[2]*a.z + h[3]*a.w
           + h[4]*b.x + h[5]*b.y + h[6]*b.z + h[7]*b.w;
    }
    if (NV > 2) {
        float4 a = __ldg((const float4*)v2 + l16 * 2);
        float4 b = __ldg((const float4*)v2 + l16 * 2 + 1);
        s2 = h[0]*a.x + h[1]*a.y + h[2]*a.z + h[3]*a.w
           + h[4]*b.x + h[5]*b.y + h[6]*b.z + h[7]*b.w;
    }
    if (NV > 3) {
        float4 a = __ldg((const float4*)v3 + l16 * 2);
        float4 b = __ldg((const float4*)v3 + l16 * 2 + 1);
        s3 = h[0]*a.x + h[1]*a.y + h[2]*a.z + h[3]*a.w
           + h[4]*b.x + h[5]*b.y + h[6]*b.z + h[7]*b.w;
    }
    #pragma unroll
    for (int o = 8; o; o >>= 1) {
        s0 += __shfl_down_sync(0xFFFFFFFFu, s0, o, 16);
        if (NV > 1) s1 += __shfl_down_sync(0xFFFFFFFFu, s1, o, 16);
        if (NV > 2) s2 += __shfl_down_sync(0xFFFFFFFFu, s2, o, 16);
        if (NV > 3) s3 += __shfl_down_sync(0xFFFFFFFFu, s3, o, 16);
    }
    if (lane == 0) {
        o0[n] = s0;
        if (NV > 1) o1[n] = s1;
        if (NV > 2) o2[n] = s2;
        if (NV > 3) o3[n] = s3;
    }
}

// ---------------- L2 scalar aggregation (gather, 8 lanes per node) ----------------
__global__ void k_s2_p(const int* __restrict__ rp1, const int* __restrict__ rp3,
                       const int* __restrict__ srcs,
                       const float* __restrict__ as1, const float* __restrict__ ad1,
                       const float* __restrict__ hw1,
                       const float* __restrict__ as3, const float* __restrict__ ad3,
                       const float* __restrict__ hw3,
                       const float* __restrict__ cb, float* __restrict__ o, int N) {
    int t = blockIdx.x * blockDim.x + threadIdx.x;
    int n = t >> 3;
    int l = t & 7;
    if (n >= N) return;
    float n1 = 0.f, d1 = 0.f, n3 = 0.f, d3 = 0.f;
    float a1 = ad1[n], a3 = ad3[n];
    int b = rp1[n], e = rp1[n + 1];
    for (int j = b + l; j < e; j += 8) {
        int s = __ldg(srcs + j);
        float x = __ldg(as1 + s) + a1;
        x = (x >= 0.f) ? x : 0.2f * x;
        float ex = __expf(x);
        d1 += ex; n1 += ex * __ldg(hw1 + s);
    }
    b = rp3[n]; e = rp3[n + 1];
    for (int j = b + l; j < e; j += 8) {
        int s = __ldg(srcs + j);
        float x = __ldg(as3 + s) + a3;
        x = (x >= 0.f) ? x : 0.2f * x;
        float ex = __expf(x);
        d3 += ex; n3 += ex * __ldg(hw3 + s);
    }
    n1 = sub8_sum(n1); d1 = sub8_sum(d1);
    n3 = sub8_sum(n3); d3 = sub8_sum(d3);
    if (l == 0)
        o[n] = ((d1 > 0.f) ? n1 / d1 : 0.f) + ((d3 > 0.f) ? n3 / d3 : 0.f) + cb[0];
}

__global__ void k_s2_m(const int* __restrict__ rp, const int* __restrict__ srcs,
                       const float* __restrict__ as_, const float* __restrict__ ad_,
                       const float* __restrict__ hw,
                       const float* __restrict__ cb, float* __restrict__ o, int N) {
    int t = blockIdx.x * blockDim.x + threadIdx.x;
    int n = t >> 3;
    int l = t & 7;
    if (n >= N) return;
    float nm = 0.f, dn = 0.f;
    float a = ad_[n];
    int b = rp[n], e = rp[n + 1];
    for (int j = b + l; j < e; j += 8) {
        int s = __ldg(srcs + j);
        float x = __ldg(as_ + s) + a;
        x = (x >= 0.f) ? x : 0.2f * x;
        float ex = __expf(x);
        dn += ex; nm += ex * __ldg(hw + s);
    }
    nm = sub8_sum(nm); dn = sub8_sum(dn);
    if (l == 0) o[n] = ((dn > 0.f) ? nm / dn : 0.f) + cb[1];
}

__global__ void k_final(const int* __restrict__ row, const int* __restrict__ col,
                        const float* __restrict__ sp, const float* __restrict__ sm,
                        const float* __restrict__ lb, float* __restrict__ out, int n) {
    int j = blockIdx.x * blockDim.x + threadIdx.x;
    if (j < n) out[j] = sp[row[j]] + sm[col[j]] + lb[0];
}

// ---------------- host ----------------
static inline int cdiv(int a, int b) { return (a + b - 1) / b; }

extern "C" void kernel_launch(void* const* d_in, const int* in_sizes, int n_in,
                              void* d_out, int out_size) {
    const int* src_pd = (const int*)d_in[0];
    const int* dst_pd = (const int*)d_in[1];
    const int* src_dp = (const int*)d_in[2];
    const int* dst_dp = (const int*)d_in[3];
    const int* src_pm = (const int*)d_in[4];
    const int* dst_pm = (const int*)d_in[5];
    const int* src_mp = (const int*)d_in[6];
    const int* dst_mp = (const int*)d_in[7];
    const int* row    = (const int*)d_in[8];
    const int* col    = (const int*)d_in[9];
    const float* x_p  = (const float*)d_in[10];
    const float* x_d  = (const float*)d_in[11];
    const float* x_m  = (const float*)d_in[12];
    const float* W1s  = (const float*)d_in[13];
    const float* W1d  = (const float*)d_in[14];
    const float* a1s  = (const float*)d_in[15];
    const float* a1d  = (const float*)d_in[16];
    const float* b1   = (const float*)d_in[17];
    const float* W2s  = (const float*)d_in[18];
    const float* W2d  = (const float*)d_in[19];
    const float* a2s  = (const float*)d_in[20];
    const float* a2d  = (const float*)d_in[21];
    const float* b2   = (const float*)d_in[22];
    const float* linw = (const float*)d_in[23];
    const float* linb = (const float*)d_in[24];
    float* out = (float*)d_out;

    int *cnt, *rowptr, *wp, *bsum, *bexcl, *srcs;
    float *vec, *u, *cb, *sp, *sm;
    __half *xh, *wt, *hspc, *hsd, *hsm;
    float *as0, *ad1, *as2, *ad3, *ad0, *as1, *ad2, *as3;
    float *as1b, *hwd, *ad2b, *as3b, *hwm, *ad1b, *as2b, *ad3b, *hwp;
    cudaGetSymbolAddress((void**)&cnt,    g_cnt);
    cudaGetSymbolAddress((void**)&rowptr, g_rowptr);
    cudaGetSymbolAddress((void**)&wp,     g_wp);
    cudaGetSymbolAddress((void**)&bsum,   g_bsum);
    cudaGetSymbolAddress((void**)&bexcl,  g_bexcl);
    cudaGetSymbolAddress((void**)&srcs,   g_srcs);
    cudaGetSymbolAddress((void**)&xh,     g_xh);
    cudaGetSymbolAddress((void**)&wt,     g_wt);
    cudaGetSymbolAddress((void**)&hspc,   g_hspc);
    cudaGetSymbolAddress((void**)&hsd,    g_hsd);
    cudaGetSymbolAddress((void**)&hsm,    g_hsm);
    cudaGetSymbolAddress((void**)&vec,    g_vec);
    cudaGetSymbolAddress((void**)&u,      g_u);
    cudaGetSymbolAddress((void**)&cb,     g_cb);
    cudaGetSymbolAddress((void**)&sp,     g_sp);
    cudaGetSymbolAddress((void**)&sm,     g_sm);
    cudaGetSymbolAddress((void**)&as0,    g_as0);
    cudaGetSymbolAddress((void**)&ad1,    g_ad1);
    cudaGetSymbolAddress((void**)&as2,    g_as2);
    cudaGetSymbolAddress((void**)&ad3,    g_ad3);
    cudaGetSymbolAddress((void**)&ad0,    g_ad0);
    cudaGetSymbolAddress((void**)&as1,    g_as1);
    cudaGetSymbolAddress((void**)&ad2,    g_ad2);
    cudaGetSymbolAddress((void**)&as3,    g_as3);
    cudaGetSymbolAddress((void**)&as1b,   g_as1b);
    cudaGetSymbolAddress((void**)&hwd,    g_hwd);
    cudaGetSymbolAddress((void**)&ad2b,   g_ad2b);
    cudaGetSymbolAddress((void**)&as3b,   g_as3b);
    cudaGetSymbolAddress((void**)&hwm,    g_hwm);
    cudaGetSymbolAddress((void**)&ad1b,   g_ad1b);
    cudaGetSymbolAddress((void**)&as2b,   g_as2b);
    cudaGetSymbolAddress((void**)&ad3b,   g_ad3b);
    cudaGetSymbolAddress((void**)&hwp,    g_hwp);

    __half* xh_p = xh;
    __half* xh_d = xh + (size_t)NP * HD;
    __half* xh_m = xh + (size_t)(NP + ND) * HD;
    __half* hs0 = hspc;
    __half* hs2 = hspc + (size_t)NP * HD;
    __half* wt0 = wt;
    __half* wt1 = wt + 1 * HD * HD;
    __half* wt2 = wt + 2 * HD * HD;
    __half* wt3 = wt + 3 * HD * HD;

    #define VEC(L, ET, W) (vec + (size_t)(((L) * 4 + (ET)) * 2 + (W)) * HD)

    // Streams/events: HOST objects created ONCE on the first call (before the
    // harness's pre-capture memory baseline) and reused.
    static cudaStream_t sA = nullptr, sB = nullptr, sC = nullptr;
    static cudaEvent_t evRoot = nullptr, evA = nullptr, evMD = nullptr;
    static cudaEvent_t evB = nullptr, evG0 = nullptr, evD = nullptr;
    static cudaEvent_t evM = nullptr, evS = nullptr;
    if (sA == nullptr) {
        cudaStreamCreateWithFlags(&sA, cudaStreamNonBlocking);
        cudaStreamCreateWithFlags(&sB, cudaStreamNonBlocking);
        cudaStreamCreateWithFlags(&sC, cudaStreamNonBlocking);
        cudaEventCreateWithFlags(&evRoot, cudaEventDisableTiming);
        cudaEventCreateWithFlags(&evA, cudaEventDisableTiming);
        cudaEventCreateWithFlags(&evMD, cudaEventDisableTiming);
        cudaEventCreateWithFlags(&evB, cudaEventDisableTiming);
        cudaEventCreateWithFlags(&evG0, cudaEventDisableTiming);
        cudaEventCreateWithFlags(&evD, cudaEventDisableTiming);
        cudaEventCreateWithFlags(&evM, cudaEventDisableTiming);
        cudaEventCreateWithFlags(&evS, cudaEventDisableTiming);
        k_consts<<<1, 64, 0, sA>>>(b2, linw, cb);
        k_consts<<<1, 64, 0, sB>>>(b2, linw, cb);
        k_consts<<<1, 64, 0, sC>>>(b2, linw, cb);
        cudaStreamSynchronize(sA);
        cudaStreamSynchronize(sB);
        cudaStreamSynchronize(sC);
    }

    cudaEventRecord(evRoot, 0);
    cudaStreamWaitEvent(sA, evRoot, 0);
    cudaStreamWaitEvent(sB, evRoot, 0);
    cudaStreamWaitEvent(sC, evRoot, 0);

    // ===== stream sA: CSR build (single fused chain) =====
    cudaMemsetAsync(cnt, 0, TOT * sizeof(int), sA);
    k_hist<<<cdiv(4 * EE, 256), 256, 0, sA>>>(dst_pd, dst_dp, dst_pm, dst_mp, cnt);
    k_scan1<<<NBLK, 1024, 0, sA>>>(cnt, rowptr, bsum);
    k_scan2<<<1, 256, 0, sA>>>(bsum, bexcl);
    k_scan3<<<NBLK, 1024, 0, sA>>>(rowptr, bexcl, wp);
    k_fill<<<cdiv(4 * EE, 256), 256, 0, sA>>>(src_pd, dst_pd, src_dp, dst_dp,
                                              src_pm, dst_pm, src_mp, dst_mp, wp, srcs);
    cudaEventRecord(evA, sA);

    const int* rp_pd = rowptr + SEG_PD;
    const int* rp_dp = rowptr + SEG_DP;
    const int* rp_pm = rowptr + SEG_PM;
    const int* rp_mp = rowptr + SEG_MP;

    // ===== stream sC: fused prep + L1 attention scalars -> evMD, then disease agg =====
    k_prep<<<cdiv(2434, 256), 256, 0, sC>>>(W1s, a1s, W1d, a1d, W2s, a2s, W2d, a2d,
                                            linw, b2, vec, u, cb);
    k_multi_dot4<<<cdiv(NP * 32, 256), 256, 0, sC>>>((const float4*)x_p, NP,
        (const float4*)VEC(0,0,0), (const float4*)VEC(0,1,1),
        (const float4*)VEC(0,2,0), (const float4*)VEC(0,3,1), as0, ad1, as2, ad3);
    k_multi_dot4<<<cdiv(ND * 32, 256), 256, 0, sC>>>((const float4*)x_d, ND,
        (const float4*)VEC(0,0,1), (const float4*)VEC(0,1,0),
        nullptr, nullptr, ad0, as1, nullptr, nullptr);
    k_multi_dot4<<<cdiv(NM * 32, 256), 256, 0, sC>>>((const float4*)x_m, NM,
        (const float4*)VEC(0,2,1), (const float4*)VEC(0,3,0),
        nullptr, nullptr, ad2, as3, nullptr, nullptr);
    cudaEventRecord(evMD, sC);

    // ===== main stream: self-contained patient GEMM chain =====
    k_cvtW<<<cdiv(HD * HD, 256), 256>>>(W1s + 0 * HD * HD, wt0);
    k_cvtW<<<cdiv(HD * HD, 256), 256>>>(W1s + 2 * HD * HD, wt2);
    k_cvt<<<cdiv(NP * HD / 4, 256), 256>>>((const float4*)x_p, (uint2*)xh_p, NP * HD / 4);
    {
        dim3 g1(cdiv(NP, 128), 2);
        k_gemm_f16<<<g1, 256>>>(xh_p, wt0, hs0, NP, HD);
    }
    cudaEventRecord(evG0, 0);
    {
        dim3 g1(cdiv(NP, 128), 2);
        k_gemm_f16<<<g1, 256>>>(xh_p, wt2, hs2, NP, HD);
    }

    // ===== stream sB: small-GEMM chain + patient agg (critical consumer) =====
    k_cvtW<<<cdiv(HD * HD, 256), 256, 0, sB>>>(W1s + 1 * HD * HD, wt1);
    k_cvtW<<<cdiv(HD * HD, 256), 256, 0, sB>>>(W1s + 3 * HD * HD, wt3);
    k_cvt<<<cdiv(ND * HD / 4, 256), 256, 0, sB>>>((const float4*)x_d, (uint2*)xh_d, ND * HD / 4);
    k_cvt<<<cdiv(NM * HD / 4, 256), 256, 0, sB>>>((const float4*)x_m, (uint2*)xh_m, NM * HD / 4);
    {
        dim3 g2(cdiv(ND, 128), 2);
        k_gemm_f16<<<g2, 256, 0, sB>>>(xh_d, wt1, hsd, ND, HD);
        dim3 g3(cdiv(NM, 128), 2);
        k_gemm_f16<<<g3, 256, 0, sB>>>(xh_m, wt3, hsm, NM, HD);
    }
    cudaStreamWaitEvent(sB, evA, 0);
    cudaStreamWaitEvent(sB, evMD, 0);
    k_agg_dot<4, true><<<cdiv(NP * 32, 256), 256, 0, sB>>>(
        rp_dp, rp_mp, srcs, as1, ad1, as3, ad3,
        (const uint4*)hsd, 16, 0, (const uint4*)hsm, 16, 0,
        b1 + 1 * HD, b1 + 3 * HD,
        VEC(1,1,1), VEC(1,2,0), VEC(1,3,1), u + 1 * HD,
        ad1b, as2b, ad3b, hwp, NP);
    cudaEventRecord(evB, sB);

    // ===== stream sC: disease agg (needs GEMM0 + CSR + multi_dots) =====
    cudaStreamWaitEvent(sC, evG0, 0);
    cudaStreamWaitEvent(sC, evA, 0);
    k_agg_dot<2, false><<<cdiv(ND * 32, 256), 256, 0, sC>>>(
        rp_pd, nullptr, srcs, as0, ad0, nullptr, nullptr,
        (const uint4*)hs0, 16, 0, nullptr, 0, 0,
        b1 + 0 * HD, nullptr,
        VEC(1,1,0), u + 0 * HD, nullptr, nullptr,
        as1b, hwd, nullptr, nullptr, ND);
    cudaEventRecord(evD, sC);

    // ===== main: medicine agg (needs GEMM2 + CSR + multi_dots) =====
    cudaStreamWaitEvent(0, evA, 0);
    cudaStreamWaitEvent(0, evMD, 0);
    k_agg_dot<3, false><<<cdiv(NM * 32, 256), 256>>>(
        rp_pm, nullptr, srcs, as2, ad2, nullptr, nullptr,
        (const uint4*)hs2, 16, 0, nullptr, 0, 0,
        b1 + 2 * HD, nullptr,
        VEC(1,2,1), VEC(1,3,0), u + 2 * HD, nullptr,
        ad2b, as3b, hwm, nullptr, NM);
    cudaEventRecord(evM, 0);

    // ===== sB: s2_m (needs patient agg [as2b, hwp] + medicine agg [ad2b]) =====
    cudaStreamWaitEvent(sB, evM, 0);
    k_s2_m<<<cdiv(NM * 8, 256), 256, 0, sB>>>(rp_pm, srcs, as2b, ad2b, hwp, cb, sm, NM);
    cudaEventRecord(evS, sB);

    // ===== main: s2_p (needs all three aggs) concurrent with s2_m =====
    cudaStreamWaitEvent(0, evB, 0);
    cudaStreamWaitEvent(0, evD, 0);
    k_s2_p<<<cdiv(NP * 8, 256), 256>>>(rp_dp, rp_mp, srcs,
        as1b, ad1b, hwd, as3b, ad3b, hwm, cb, sp, NP);

    // ===== join + head =====
    cudaStreamWaitEvent(0, evS, 0);
    k_final<<<cdiv(ELN, 256), 256>>>(row, col, sp, sm, linb, out, ELN);
    #undef VEC
}

// round 17
// speedup vs baseline: 1.1112x; 1.0049x over previous
#include <cuda_runtime.h>
#include <cuda_fp16.h>
#include <cuda_bf16.h>

#define NP 100000
#define ND 30000
#define NM 20000
#define EE 600000
#define ELN 200000
#define HD 128
#define CD 64

// CSR segment layout over concatenated dst spaces:
// [pd: ND rows][dp: NP rows][pm: NM rows][mp: NP rows]
#define SEG_PD 0
#define SEG_DP (ND)
#define SEG_PM (ND + NP)
#define SEG_MP (ND + NP + NM)
#define TOT    (ND + NP + NM + NP)          // 250000
#define NBLK   ((TOT + 1023) / 1024)        // 245
#define EQ     (EE / 4)                     // int4 chunks per relation

// ---------------- static device scratch ----------------
__device__ __align__(256) int g_cnt[TOT];
__device__ __align__(256) int g_rowptr[TOT + 1];
__device__ __align__(256) int g_wp[TOT];
__device__ __align__(256) int g_bsum[NBLK];
__device__ __align__(256) int g_bexcl[NBLK];
__device__ __align__(256) int g_srcs[4 * EE];

__device__ __align__(256) __half g_xh[(NP + ND + NM) * HD];  // fp16 embeddings
__device__ __align__(256) __half g_wt[4 * HD * HD];          // fp16 transposed W1s[et]
__device__ __align__(256) __half g_hspc[NP * 256];  // [hs0: x_p@W1s0][hs2: x_p@W1s2]
__device__ __align__(256) __half g_hsd [ND * HD];
__device__ __align__(256) __half g_hsm [NM * HD];
__device__ __align__(256) float g_vec[16 * HD];
__device__ __align__(256) float g_u[3 * HD];
__device__ __align__(256) float g_cb[2];
// L1 attention scalars (from raw embeddings)
__device__ __align__(256) float g_as0[NP], g_ad1[NP], g_as2[NP], g_ad3[NP];
__device__ __align__(256) float g_ad0[ND], g_as1[ND];
__device__ __align__(256) float g_ad2[NM], g_as3[NM];
// L2 attention scalars + h.u dots (from fused agg)
__device__ __align__(256) float g_as1b[ND], g_hwd[ND];
__device__ __align__(256) float g_ad2b[NM], g_as3b[NM], g_hwm[NM];
__device__ __align__(256) float g_ad1b[NP], g_as2b[NP], g_ad3b[NP], g_hwp[NP];
__device__ __align__(256) float g_sp[NP], g_sm[NM];

// ---------------- helpers ----------------
__device__ __forceinline__ float warp_sum(float v) {
    #pragma unroll
    for (int o = 16; o; o >>= 1) v += __shfl_down_sync(0xFFFFFFFFu, v, o);
    return v;
}
__device__ __forceinline__ float sub8_sum(float v) {
    v += __shfl_down_sync(0xFFFFFFFFu, v, 4, 8);
    v += __shfl_down_sync(0xFFFFFFFFu, v, 2, 8);
    v += __shfl_down_sync(0xFFFFFFFFu, v, 1, 8);
    return v;
}
__device__ __forceinline__ float dot4(float4 a, float4 b) {
    return a.x * b.x + a.y * b.y + a.z * b.z + a.w * b.w;
}

// ---------------- prep kernels ----------------
// WT[n][k] = fp16(W[k][n]);  W: [128][128] fp32 row-major (k-major)
__global__ void k_cvtW(const float* __restrict__ W, __half* __restrict__ WT) {
    int i = blockIdx.x * blockDim.x + threadIdx.x;   // 16384
    int n = i >> 7, k = i & 127;
    WT[(size_t)n * HD + k] = __float2half_rn(W[(size_t)k * HD + n]);
}

// fused: L1 vecs [0,1024) | L2 vecs [1024,2048) | uvecs [2048,2432) | cb [2432,2434)
__global__ void k_prep(const float* __restrict__ W1s, const float* __restrict__ a1s,
                       const float* __restrict__ W1d, const float* __restrict__ a1d,
                       const float* __restrict__ W2s, const float* __restrict__ a2s,
                       const float* __restrict__ W2d, const float* __restrict__ a2d,
                       const float* __restrict__ linw, const float* __restrict__ b2,
                       float* __restrict__ vec, float* __restrict__ u,
                       float* __restrict__ cb) {
    int idx = blockIdx.x * blockDim.x + threadIdx.x;
    if (idx < 1024) {
        int k = idx % HD, w = (idx / HD) & 1, et = idx / (2 * HD);
        const float* W = w ? W1d : W1s;
        const float* a = w ? a1d : a1s;
        const float* Wrow = W + (size_t)et * HD * HD + (size_t)k * HD;
        const float* av = a + (size_t)et * HD;
        float s = 0.f;
        for (int j = 0; j < HD; j++) s += Wrow[j] * av[j];
        vec[idx] = s;
    } else if (idx < 2048) {
        int li = idx - 1024;
        int k = li % HD, w = (li / HD) & 1, et = li / (2 * HD);
        const float* W = w ? W2d : W2s;
        const float* a = w ? a2d : a2s;
        const float* Wrow = W + (size_t)et * HD * CD + (size_t)k * CD;
        const float* av = a + (size_t)et * CD;
        float s = 0.f;
        for (int j = 0; j < CD; j++) s += Wrow[j] * av[j];
        vec[8 * HD + li] = s;
    } else if (idx < 2432) {
        int li = idx - 2048;
        int e = li / HD, k = li % HD;
        const float* W = W2s + (size_t)(e + 1) * HD * CD + (size_t)k * CD;
        const float* w = linw + ((e == 1) ? CD : 0);
        float s = 0.f;
        for (int j = 0; j < CD; j++) s += W[j] * w[j];
        u[li] = s;
    } else if (idx == 2432) {
        float s = 0.f;
        for (int j = 0; j < CD; j++) s += (b2[CD + j] + b2[3 * CD + j]) * linw[j];
        cb[0] = s;
    } else if (idx == 2433) {
        float s = 0.f;
        for (int j = 0; j < CD; j++) s += b2[2 * CD + j] * linw[CD + j];
        cb[1] = s;
    }
}

// DIM=128: one float4 per lane per operand; also emits fp16 copy of x
__global__ void k_multi_dot4(const float4* __restrict__ x, int N,
                             const float4* __restrict__ v0, const float4* __restrict__ v1,
                             const float4* __restrict__ v2, const float4* __restrict__ v3,
                             float* __restrict__ o0, float* __restrict__ o1,
                             float* __restrict__ o2, float* __restrict__ o3,
                             uint2* __restrict__ xh) {
    int warp = (blockIdx.x * blockDim.x + threadIdx.x) >> 5;
    int lane = threadIdx.x & 31;
    if (warp >= N) return;
    float4 xv = __ldg(x + (size_t)warp * 32 + lane);
    {
        __half2 lo = __floats2half2_rn(xv.x, xv.y);
        __half2 hi = __floats2half2_rn(xv.z, xv.w);
        uint2 r;
        r.x = *(unsigned*)&lo;
        r.y = *(unsigned*)&hi;
        xh[(size_t)warp * 32 + lane] = r;
    }
    float s0 = dot4(xv, __ldg(v0 + lane));
    float s1 = v1 ? dot4(xv, __ldg(v1 + lane)) : 0.f;
    float s2 = v2 ? dot4(xv, __ldg(v2 + lane)) : 0.f;
    float s3 = v3 ? dot4(xv, __ldg(v3 + lane)) : 0.f;
    s0 = warp_sum(s0);
    if (v1) s1 = warp_sum(s1);
    if (v2) s2 = warp_sum(s2);
    if (v3) s3 = warp_sum(s3);
    if (lane == 0) {
        o0[warp] = s0;
        if (o1) o1[warp] = s1;
        if (o2) o2[warp] = s2;
        if (o3) o3[warp] = s3;
    }
}

// ---------------- CSR build (int4-vectorized hist/fill) ----------------
__global__ void k_hist4(const int4* __restrict__ d_pd, const int4* __restrict__ d_dp,
                        const int4* __restrict__ d_pm, const int4* __restrict__ d_mp,
                        int* __restrict__ cnt) {
    int idx = blockIdx.x * blockDim.x + threadIdx.x;
    if (idx >= 4 * EQ) return;
    int r = idx / EQ, e = idx - r * EQ;
    const int4* p;
    int base;
    if (r == 0)      { p = d_pd; base = SEG_PD; }
    else if (r == 1) { p = d_dp; base = SEG_DP; }
    else if (r == 2) { p = d_pm; base = SEG_PM; }
    else             { p = d_mp; base = SEG_MP; }
    int4 v = __ldg(p + e);
    atomicAdd(cnt + base + v.x, 1);
    atomicAdd(cnt + base + v.y, 1);
    atomicAdd(cnt + base + v.z, 1);
    atomicAdd(cnt + base + v.w, 1);
}

__global__ void k_scan1(const int* __restrict__ cnt, int* __restrict__ rp,
                        int* __restrict__ bsum) {
    __shared__ int sh[1024];
    int t = threadIdx.x;
    int i = blockIdx.x * 1024 + t;
    int v = (i < TOT) ? cnt[i] : 0;
    sh[t] = v;
    __syncthreads();
    for (int o = 1; o < 1024; o <<= 1) {
        int x = (t >= o) ? sh[t - o] : 0;
        __syncthreads();
        sh[t] += x;
        __syncthreads();
    }
    if (i < TOT) rp[i] = sh[t] - v;
    if (t == 1023) bsum[blockIdx.x] = sh[1023];
}

__global__ void k_scan2(const int* __restrict__ bsum, int* __restrict__ bexcl) {
    __shared__ int sh[256];
    int t = threadIdx.x;
    int v = (t < NBLK) ? bsum[t] : 0;
    sh[t] = v;
    __syncthreads();
    for (int o = 1; o < 256; o <<= 1) {
        int x = (t >= o) ? sh[t - o] : 0;
        __syncthreads();
        sh[t] += x;
        __syncthreads();
    }
    if (t < NBLK) bexcl[t] = sh[t] - v;
}

__global__ void k_scan3(int* __restrict__ rp, const int* __restrict__ bexcl,
                        int* __restrict__ wp) {
    int i = blockIdx.x * 1024 + threadIdx.x;
    if (i < TOT) {
        int v = rp[i] + bexcl[blockIdx.x];
        rp[i] = v;
        wp[i] = v;
    }
    if (i == 0) rp[TOT] = 4 * EE;
}

__global__ void k_fill4(const int4* __restrict__ s_pd, const int4* __restrict__ d_pd,
                        const int4* __restrict__ s_dp, const int4* __restrict__ d_dp,
                        const int4* __restrict__ s_pm, const int4* __restrict__ d_pm,
                        const int4* __restrict__ s_mp, const int4* __restrict__ d_mp,
                        int* __restrict__ wp, int* __restrict__ srcs) {
    int idx = blockIdx.x * blockDim.x + threadIdx.x;
    if (idx >= 4 * EQ) return;
    int r = idx / EQ, e = idx - r * EQ;
    const int4 *pd, *ps;
    int base;
    if (r == 0)      { pd = d_pd; ps = s_pd; base = SEG_PD; }
    else if (r == 1) { pd = d_dp; ps = s_dp; base = SEG_DP; }
    else if (r == 2) { pd = d_pm; ps = s_pm; base = SEG_PM; }
    else             { pd = d_mp; ps = s_mp; base = SEG_MP; }
    int4 d = __ldg(pd + e);
    int4 s = __ldg(ps + e);
    srcs[atomicAdd(wp + base + d.x, 1)] = s.x;
    srcs[atomicAdd(wp + base + d.y, 1)] = s.y;
    srcs[atomicAdd(wp + base + d.z, 1)] = s.z;
    srcs[atomicAdd(wp + base + d.w, 1)] = s.w;
}

// ---------------- fp16 GEMM: C[M,64/block] = A[M,128] @ WT^T, mma m16n8k16 ----------------
__device__ __forceinline__ void mma_f16(float* d, const unsigned* a, const unsigned* b) {
    asm volatile(
        "mma.sync.aligned.m16n8k16.row.col.f32.f16.f16.f32 "
        "{%0,%1,%2,%3}, {%4,%5,%6,%7}, {%8,%9}, {%0,%1,%2,%3};"
        : "+f"(d[0]), "+f"(d[1]), "+f"(d[2]), "+f"(d[3])
        : "r"(a[0]), "r"(a[1]), "r"(a[2]), "r"(a[3]), "r"(b[0]), "r"(b[1]));
}

__global__ __launch_bounds__(256) void k_gemm_f16(const __half* __restrict__ A,
                                                  const __half* __restrict__ WT,
                                                  __half* __restrict__ C,
                                                  int M, int ldc) {
    __shared__ __half As[2][128][40];    // u32 bank (20r + t) % 32: conflict-free
    __shared__ __half Bsn[2][64][40];    // [n][k]
    int tid = threadIdx.x;
    int lane = tid & 31, warp = tid >> 5;
    int gid = lane >> 2, tig = lane & 3;
    int wm = warp & 3, wn = warp >> 2;
    int m0 = blockIdx.x * 128, n0 = blockIdx.y * 64;

    float acc[2][4][4];
    #pragma unroll
    for (int i = 0; i < 2; i++)
        #pragma unroll
        for (int j = 0; j < 4; j++)
            #pragma unroll
            for (int l = 0; l < 4; l++) acc[i][j][l] = 0.f;

    auto load_stage = [&](int kb, int buf) {
        #pragma unroll
        for (int i = 0; i < 2; i++) {
            int f = i * 256 + tid;          // 0..511
            int m = f >> 2;
            int c8 = (f & 3) * 8;
            const __half* src = A + (size_t)(m0 + m) * 128 + kb * 32 + c8;
            unsigned ds = (unsigned)__cvta_generic_to_shared(&As[buf][m][c8]);
            int p = (m0 + m < M) ? 16 : 0;
            asm volatile("cp.async.cg.shared.global [%0], [%1], 16, %2;"
                         :: "r"(ds), "l"(src), "r"(p));
        }
        {
            int n = tid >> 2;                // 0..63
            int c8 = (tid & 3) * 8;
            const __half* src = WT + (size_t)(n0 + n) * 128 + kb * 32 + c8;
            unsigned ds = (unsigned)__cvta_generic_to_shared(&Bsn[buf][n][c8]);
            asm volatile("cp.async.cg.shared.global [%0], [%1], 16, 16;"
                         :: "r"(ds), "l"(src));
        }
        asm volatile("cp.async.commit_group;");
    };

    load_stage(0, 0);

    for (int kb = 0; kb < 4; kb++) {
        if (kb < 3) {
            load_stage(kb + 1, (kb + 1) & 1);
            asm volatile("cp.async.wait_group 1;");
        } else {
            asm volatile("cp.async.wait_group 0;");
        }
        __syncthreads();
        int buf = kb & 1;
        #pragma unroll
        for (int ks = 0; ks < 2; ks++) {
            int kk = ks * 16;
            unsigned a[2][4], b[4][2];
            #pragma unroll
            for (int ms = 0; ms < 2; ms++) {
                int r = wm * 32 + ms * 16 + gid;
                a[ms][0] = *(const unsigned*)&As[buf][r][kk + tig * 2];
                a[ms][1] = *(const unsigned*)&As[buf][r + 8][kk + tig * 2];
                a[ms][2] = *(const unsigned*)&As[buf][r][kk + 8 + tig * 2];
                a[ms][3] = *(const unsigned*)&As[buf][r + 8][kk + 8 + tig * 2];
            }
            #pragma unroll
            for (int ns = 0; ns < 4; ns++) {
                int c = wn * 32 + ns * 8 + gid;
                b[ns][0] = *(const unsigned*)&Bsn[buf][c][kk + tig * 2];
                b[ns][1] = *(const unsigned*)&Bsn[buf][c][kk + 8 + tig * 2];
            }
            #pragma unroll
            for (int ms = 0; ms < 2; ms++)
                #pragma unroll
                for (int ns = 0; ns < 4; ns++) mma_f16(acc[ms][ns], a[ms], b[ns]);
        }
        __syncthreads();
    }

    #pragma unroll
    for (int ms = 0; ms < 2; ms++) {
        int r = m0 + wm * 32 + ms * 16 + gid;
        #pragma unroll
        for (int ns = 0; ns < 4; ns++) {
            int c = n0 + wn * 32 + ns * 8 + 2 * tig;
            if (r < M)
                *(__half2*)(C + (size_t)r * ldc + c) = __floats2half2_rn(acc[ms][ns][0], acc[ms][ns][1]);
            if (r + 8 < M)
                *(__half2*)(C + (size_t)(r + 8) * ldc + c) = __floats2half2_rn(acc[ms][ns][2], acc[ms][ns][3]);
        }
    }
}

// ---------------- agg segment: shuffle-broadcast indices + 2-stage pipeline ----------------
__device__ __forceinline__ void agg_segment(
    int b, int e, const int* __restrict__ srcs,
    const float* __restrict__ as_, float adv,
    const uint4* __restrict__ hs, int srow, int soff,
    int lane, int half, int l16, float* acc, float& den)
{
    for (int c0 = b; c0 < e; c0 += 32) {
        int idx = c0 + lane;
        int sv = (idx < e) ? __ldg(srcs + idx) : 0;   // coalesced index chunk
        int cnt = min(32, e - c0);
        int s_c = __shfl_sync(0xFFFFFFFFu, sv, min(half, cnt - 1));
        float a_c = __ldg(as_ + s_c);
        uint4 h_c = __ldg(hs + (size_t)s_c * srow + soff + l16);
        for (int t2 = 0; t2 < cnt; t2 += 2) {
            int t2n = t2 + 2;
            int sh = (t2n < cnt) ? min(t2n + half, cnt - 1) : 0;
            int s_n = __shfl_sync(0xFFFFFFFFu, sv, sh);
            float a_n = __ldg(as_ + s_n);
            uint4 h_n = __ldg(hs + (size_t)s_n * srow + soff + l16);
            float x = a_c + adv;
            x = (x >= 0.f) ? x : 0.2f * x;
            float ex = (t2 + half < cnt) ? __expf(x) : 0.f;
            den += ex;
            float2 f0 = __half22float2(*(__half2*)&h_c.x);
            float2 f1 = __half22float2(*(__half2*)&h_c.y);
            float2 f2 = __half22float2(*(__half2*)&h_c.z);
            float2 f3 = __half22float2(*(__half2*)&h_c.w);
            acc[0] += ex * f0.x; acc[1] += ex * f0.y;
            acc[2] += ex * f1.x; acc[3] += ex * f1.y;
            acc[4] += ex * f2.x; acc[5] += ex * f2.y;
            acc[6] += ex * f3.x; acc[7] += ex * f3.y;
            s_c = s_n; a_c = a_n; h_c = h_n;
        }
    }
}

// ---------------- fused L1 aggregation: gather + softmax + relu + dots ----------------
template<int NV, bool DUAL>
__global__ __launch_bounds__(256) void k_agg_dot(
    const int* __restrict__ rpA, const int* __restrict__ rpB,
    const int* __restrict__ srcs,
    const float* __restrict__ asA, const float* __restrict__ adA,
    const float* __restrict__ asB, const float* __restrict__ adB,
    const uint4* __restrict__ hsA, int srowA, int soffA,
    const uint4* __restrict__ hsB, int srowB, int soffB,
    const float* __restrict__ ba, const float* __restrict__ bb,
    const float* __restrict__ v0, const float* __restrict__ v1,
    const float* __restrict__ v2, const float* __restrict__ v3,
    float* __restrict__ o0, float* __restrict__ o1,
    float* __restrict__ o2, float* __restrict__ o3, int N)
{
    int n = (blockIdx.x * blockDim.x + threadIdx.x) >> 5;
    int lane = threadIdx.x & 31;
    if (n >= N) return;
    int half = lane >> 4, l16 = lane & 15;

    float acc[8], den = 0.f;
    #pragma unroll
    for (int i = 0; i < 8; i++) acc[i] = 0.f;
    agg_segment(rpA[n], rpA[n + 1], srcs, asA, adA[n], hsA, srowA, soffA,
                lane, half, l16, acc, den);

    float accB[8], denB = 0.f;
    if (DUAL) {
        #pragma unroll
        for (int i = 0; i < 8; i++) accB[i] = 0.f;
        agg_segment(rpB[n], rpB[n + 1], srcs, asB, adB[n], hsB, srowB, soffB,
                    lane, half, l16, accB, denB);
    }

    #pragma unroll
    for (int i = 0; i < 8; i++) acc[i] += __shfl_down_sync(0xFFFFFFFFu, acc[i], 16);
    den += __shfl_down_sync(0xFFFFFFFFu, den, 16);
    if (DUAL) {
        #pragma unroll
        for (int i = 0; i < 8; i++) accB[i] += __shfl_down_sync(0xFFFFFFFFu, accB[i], 16);
        denB += __shfl_down_sync(0xFFFFFFFFu, denB, 16);
    }

    float r = (den > 0.f) ? 1.f / den : 0.f;
    float4 bv0 = __ldg((const float4*)ba + l16 * 2);
    float4 bv1 = __ldg((const float4*)ba + l16 * 2 + 1);
    float h[8];
    h[0] = acc[0] * r + bv0.x; h[1] = acc[1] * r + bv0.y;
    h[2] = acc[2] * r + bv0.z; h[3] = acc[3] * r + bv0.w;
    h[4] = acc[4] * r + bv1.x; h[5] = acc[5] * r + bv1.y;
    h[6] = acc[6] * r + bv1.z; h[7] = acc[7] * r + bv1.w;
    if (DUAL) {
        float rB = (denB > 0.f) ? 1.f / denB : 0.f;
        float4 c0 = __ldg((const float4*)bb + l16 * 2);
        float4 c1 = __ldg((const float4*)bb + l16 * 2 + 1);
        h[0] += accB[0] * rB + c0.x; h[1] += accB[1] * rB + c0.y;
        h[2] += accB[2] * rB + c0.z; h[3] += accB[3] * rB + c0.w;
        h[4] += accB[4] * rB + c1.x; h[5] += accB[5] * rB + c1.y;
        h[6] += accB[6] * rB + c1.z; h[7] += accB[7] * rB + c1.w;
    }
    #pragma unroll
    for (int i = 0; i < 8; i++) h[i] = fmaxf(h[i], 0.f);

    float s0 = 0.f, s1 = 0.f, s2 = 0.f, s3 = 0.f;
    {
        float4 a = __ldg((const float4*)v0 + l16 * 2);
        float4 b = __ldg((const float4*)v0 + l16 * 2 + 1);
        s0 = h[0]*a.x + h[1]*a.y + h[2]*a.z + h[3]*a.w
           + h[4]*b.x + h[5]*b.y + h[6]*b.z + h[7]*b.w;
    }
    if (NV > 1) {
        float4 a = __ldg((const float4*)v1 + l16 * 2);
        float4 b = __ldg((const float4*)v1 + l16 * 2 + 1);
        s1 = h[0]*a.x + h[1]*a.y + h[2]*a.z + h[3]*a.w
           + h[4]*b.x + h[5]*b.y + h[6]*b.z + h[7]*b.w;
    }
    if (NV > 2) {
        float4 a = __ldg((const float4*)v2 + l16 * 2);
        float4 b = __ldg((const float4*)v2 + l16 * 2 + 1);
        s2 = h[0]*a.x + h[1]*a.y + h[2]*a.z + h[3]*a.w
           + h[4]*b.x + h[5]*b.y + h[6]*b.z + h[7]*b.w;
    }
    if (NV > 3) {
        float4 a = __ldg((const float4*)v3 + l16 * 2);
        float4 b = __ldg((const float4*)v3 + l16 * 2 + 1);
        s3 = h[0]*a.x + h[1]*a.y + h[2]*a.z + h[3]*a.w
           + h[4]*b.x + h[5]*b.y + h[6]*b.z + h[7]*b.w;
    }
    #pragma unroll
    for (int o = 8; o; o >>= 1) {
        s0 += __shfl_down_sync(0xFFFFFFFFu, s0, o, 16);
        if (NV > 1) s1 += __shfl_down_sync(0xFFFFFFFFu, s1, o, 16);
        if (NV > 2) s2 += __shfl_down_sync(0xFFFFFFFFu, s2, o, 16);
        if (NV > 3) s3 += __shfl_down_sync(0xFFFFFFFFu, s3, o, 16);
    }
    if (lane == 0) {
        o0[n] = s0;
        if (NV > 1) o1[n] = s1;
        if (NV > 2) o2[n] = s2;
        if (NV > 3) o3[n] = s3;
    }
}

// ---------------- L2 scalar aggregation (gather, 8 lanes per node) ----------------
__global__ void k_s2_p(const int* __restrict__ rp1, const int* __restrict__ rp3,
                       const int* __restrict__ srcs,
                       const float* __restrict__ as1, const float* __restrict__ ad1,
                       const float* __restrict__ hw1,
                       const float* __restrict__ as3, const float* __restrict__ ad3,
                       const float* __restrict__ hw3,
                       const float* __restrict__ cb, float* __restrict__ o, int N) {
    int t = blockIdx.x * blockDim.x + threadIdx.x;
    int n = t >> 3;
    int l = t & 7;
    if (n >= N) return;
    float n1 = 0.f, d1 = 0.f, n3 = 0.f, d3 = 0.f;
    float a1 = ad1[n], a3 = ad3[n];
    int b = rp1[n], e = rp1[n + 1];
    for (int j = b + l; j < e; j += 8) {
        int s = __ldg(srcs + j);
        float x = __ldg(as1 + s) + a1;
        x = (x >= 0.f) ? x : 0.2f * x;
        float ex = __expf(x);
        d1 += ex; n1 += ex * __ldg(hw1 + s);
    }
    b = rp3[n]; e = rp3[n + 1];
    for (int j = b + l; j < e; j += 8) {
        int s = __ldg(srcs + j);
        float x = __ldg(as3 + s) + a3;
        x = (x >= 0.f) ? x : 0.2f * x;
        float ex = __expf(x);
        d3 += ex; n3 += ex * __ldg(hw3 + s);
    }
    n1 = sub8_sum(n1); d1 = sub8_sum(d1);
    n3 = sub8_sum(n3); d3 = sub8_sum(d3);
    if (l == 0)
        o[n] = ((d1 > 0.f) ? n1 / d1 : 0.f) + ((d3 > 0.f) ? n3 / d3 : 0.f) + cb[0];
}

__global__ void k_s2_m(const int* __restrict__ rp, const int* __restrict__ srcs,
                       const float* __restrict__ as_, const float* __restrict__ ad_,
                       const float* __restrict__ hw,
                       const float* __restrict__ cb, float* __restrict__ o, int N) {
    int t = blockIdx.x * blockDim.x + threadIdx.x;
    int n = t >> 3;
    int l = t & 7;
    if (n >= N) return;
    float nm = 0.f, dn = 0.f;
    float a = ad_[n];
    int b = rp[n], e = rp[n + 1];
    for (int j = b + l; j < e; j += 8) {
        int s = __ldg(srcs + j);
        float x = __ldg(as_ + s) + a;
        x = (x >= 0.f) ? x : 0.2f * x;
        float ex = __expf(x);
        dn += ex; nm += ex * __ldg(hw + s);
    }
    nm = sub8_sum(nm); dn = sub8_sum(dn);
    if (l == 0) o[n] = ((dn > 0.f) ? nm / dn : 0.f) + cb[1];
}

__global__ void k_final(const int* __restrict__ row, const int* __restrict__ col,
                        const float* __restrict__ sp, const float* __restrict__ sm,
                        const float* __restrict__ lb, float* __restrict__ out, int n) {
    int j = blockIdx.x * blockDim.x + threadIdx.x;
    if (j < n) out[j] = sp[row[j]] + sm[col[j]] + lb[0];
}

// ---------------- host ----------------
static inline int cdiv(int a, int b) { return (a + b - 1) / b; }

extern "C" void kernel_launch(void* const* d_in, const int* in_sizes, int n_in,
                              void* d_out, int out_size) {
    const int* src_pd = (const int*)d_in[0];
    const int* dst_pd = (const int*)d_in[1];
    const int* src_dp = (const int*)d_in[2];
    const int* dst_dp = (const int*)d_in[3];
    const int* src_pm = (const int*)d_in[4];
    const int* dst_pm = (const int*)d_in[5];
    const int* src_mp = (const int*)d_in[6];
    const int* dst_mp = (const int*)d_in[7];
    const int* row    = (const int*)d_in[8];
    const int* col    = (const int*)d_in[9];
    const float* x_p  = (const float*)d_in[10];
    const float* x_d  = (const float*)d_in[11];
    const float* x_m  = (const float*)d_in[12];
    const float* W1s  = (const float*)d_in[13];
    const float* W1d  = (const float*)d_in[14];
    const float* a1s  = (const float*)d_in[15];
    const float* a1d  = (const float*)d_in[16];
    const float* b1   = (const float*)d_in[17];
    const float* W2s  = (const float*)d_in[18];
    const float* W2d  = (const float*)d_in[19];
    const float* a2s  = (const float*)d_in[20];
    const float* a2d  = (const float*)d_in[21];
    const float* b2   = (const float*)d_in[22];
    const float* linw = (const float*)d_in[23];
    const float* linb = (const float*)d_in[24];
    float* out = (float*)d_out;

    int *cnt, *rowptr, *wp, *bsum, *bexcl, *srcs;
    float *vec, *u, *cb, *sp, *sm;
    __half *xh, *wt, *hspc, *hsd, *hsm;
    float *as0, *ad1, *as2, *ad3, *ad0, *as1, *ad2, *as3;
    float *as1b, *hwd, *ad2b, *as3b, *hwm, *ad1b, *as2b, *ad3b, *hwp;
    cudaGetSymbolAddress((void**)&cnt,    g_cnt);
    cudaGetSymbolAddress((void**)&rowptr, g_rowptr);
    cudaGetSymbolAddress((void**)&wp,     g_wp);
    cudaGetSymbolAddress((void**)&bsum,   g_bsum);
    cudaGetSymbolAddress((void**)&bexcl,  g_bexcl);
    cudaGetSymbolAddress((void**)&srcs,   g_srcs);
    cudaGetSymbolAddress((void**)&xh,     g_xh);
    cudaGetSymbolAddress((void**)&wt,     g_wt);
    cudaGetSymbolAddress((void**)&hspc,   g_hspc);
    cudaGetSymbolAddress((void**)&hsd,    g_hsd);
    cudaGetSymbolAddress((void**)&hsm,    g_hsm);
    cudaGetSymbolAddress((void**)&vec,    g_vec);
    cudaGetSymbolAddress((void**)&u,      g_u);
    cudaGetSymbolAddress((void**)&cb,     g_cb);
    cudaGetSymbolAddress((void**)&sp,     g_sp);
    cudaGetSymbolAddress((void**)&sm,     g_sm);
    cudaGetSymbolAddress((void**)&as0,    g_as0);
    cudaGetSymbolAddress((void**)&ad1,    g_ad1);
    cudaGetSymbolAddress((void**)&as2,    g_as2);
    cudaGetSymbolAddress((void**)&ad3,    g_ad3);
    cudaGetSymbolAddress((void**)&ad0,    g_ad0);
    cudaGetSymbolAddress((void**)&as1,    g_as1);
    cudaGetSymbolAddress((void**)&ad2,    g_ad2);
    cudaGetSymbolAddress((void**)&as3,    g_as3);
    cudaGetSymbolAddress((void**)&as1b,   g_as1b);
    cudaGetSymbolAddress((void**)&hwd,    g_hwd);
    cudaGetSymbolAddress((void**)&ad2b,   g_ad2b);
    cudaGetSymbolAddress((void**)&as3b,   g_as3b);
    cudaGetSymbolAddress((void**)&hwm,    g_hwm);
    cudaGetSymbolAddress((void**)&ad1b,   g_ad1b);
    cudaGetSymbolAddress((void**)&as2b,   g_as2b);
    cudaGetSymbolAddress((void**)&ad3b,   g_ad3b);
    cudaGetSymbolAddress((void**)&hwp,    g_hwp);

    __half* xh_p = xh;
    __half* xh_d = xh + (size_t)NP * HD;
    __half* xh_m = xh + (size_t)(NP + ND) * HD;
    __half* hs0 = hspc;
    __half* hs2 = hspc + (size_t)NP * HD;
    __half* wt0 = wt;
    __half* wt1 = wt + 1 * HD * HD;
    __half* wt2 = wt + 2 * HD * HD;
    __half* wt3 = wt + 3 * HD * HD;

    #define VEC(L, ET, W) (vec + (size_t)(((L) * 4 + (ET)) * 2 + (W)) * HD)

    // Streams/events: HOST objects created ONCE on the first call (before the
    // harness's pre-capture memory baseline) and reused.
    static cudaStream_t sA = nullptr, sB = nullptr, sC = nullptr;
    static cudaEvent_t evRoot = nullptr, evA = nullptr, evMD = nullptr;
    static cudaEvent_t evB = nullptr, evG0 = nullptr, evD = nullptr;
    static cudaEvent_t evM = nullptr, evS = nullptr, evXP = nullptr;
    if (sA == nullptr) {
        cudaStreamCreateWithFlags(&sA, cudaStreamNonBlocking);
        cudaStreamCreateWithFlags(&sB, cudaStreamNonBlocking);
        cudaStreamCreateWithFlags(&sC, cudaStreamNonBlocking);
        cudaEventCreateWithFlags(&evRoot, cudaEventDisableTiming);
        cudaEventCreateWithFlags(&evA, cudaEventDisableTiming);
        cudaEventCreateWithFlags(&evMD, cudaEventDisableTiming);
        cudaEventCreateWithFlags(&evB, cudaEventDisableTiming);
        cudaEventCreateWithFlags(&evG0, cudaEventDisableTiming);
        cudaEventCreateWithFlags(&evD, cudaEventDisableTiming);
        cudaEventCreateWithFlags(&evM, cudaEventDisableTiming);
        cudaEventCreateWithFlags(&evS, cudaEventDisableTiming);
        cudaEventCreateWithFlags(&evXP, cudaEventDisableTiming);
        k_prep<<<cdiv(2434, 256), 256, 0, sA>>>(W1s, a1s, W1d, a1d, W2s, a2s, W2d, a2d,
                                                linw, b2, vec, u, cb);
        k_prep<<<cdiv(2434, 256), 256, 0, sB>>>(W1s, a1s, W1d, a1d, W2s, a2s, W2d, a2d,
                                                linw, b2, vec, u, cb);
        k_prep<<<cdiv(2434, 256), 256, 0, sC>>>(W1s, a1s, W1d, a1d, W2s, a2s, W2d, a2d,
                                                linw, b2, vec, u, cb);
        cudaStreamSynchronize(sA);
        cudaStreamSynchronize(sB);
        cudaStreamSynchronize(sC);
    }

    cudaEventRecord(evRoot, 0);
    cudaStreamWaitEvent(sA, evRoot, 0);
    cudaStreamWaitEvent(sB, evRoot, 0);
    cudaStreamWaitEvent(sC, evRoot, 0);

    // ===== stream sA: CSR build (single fused chain, int4 hist/fill) =====
    cudaMemsetAsync(cnt, 0, TOT * sizeof(int), sA);
    k_hist4<<<cdiv(4 * EQ, 256), 256, 0, sA>>>((const int4*)dst_pd, (const int4*)dst_dp,
                                               (const int4*)dst_pm, (const int4*)dst_mp, cnt);
    k_scan1<<<NBLK, 1024, 0, sA>>>(cnt, rowptr, bsum);
    k_scan2<<<1, 256, 0, sA>>>(bsum, bexcl);
    k_scan3<<<NBLK, 1024, 0, sA>>>(rowptr, bexcl, wp);
    k_fill4<<<cdiv(4 * EQ, 256), 256, 0, sA>>>(
        (const int4*)src_pd, (const int4*)dst_pd, (const int4*)src_dp, (const int4*)dst_dp,
        (const int4*)src_pm, (const int4*)dst_pm, (const int4*)src_mp, (const int4*)dst_mp,
        wp, srcs);
    cudaEventRecord(evA, sA);

    const int* rp_pd = rowptr + SEG_PD;
    const int* rp_dp = rowptr + SEG_DP;
    const int* rp_pm = rowptr + SEG_PM;
    const int* rp_mp = rowptr + SEG_MP;

    // ===== stream sC: fused prep + L1 attention scalars (+ fp16 cvt) =====
    k_prep<<<cdiv(2434, 256), 256, 0, sC>>>(W1s, a1s, W1d, a1d, W2s, a2s, W2d, a2d,
                                            linw, b2, vec, u, cb);
    k_multi_dot4<<<cdiv(NP * 32, 256), 256, 0, sC>>>((const float4*)x_p, NP,
        (const float4*)VEC(0,0,0), (const float4*)VEC(0,1,1),
        (const float4*)VEC(0,2,0), (const float4*)VEC(0,3,1), as0, ad1, as2, ad3,
        (uint2*)xh_p);
    cudaEventRecord(evXP, sC);
    k_multi_dot4<<<cdiv(ND * 32, 256), 256, 0, sC>>>((const float4*)x_d, ND,
        (const float4*)VEC(0,0,1), (const float4*)VEC(0,1,0),
        nullptr, nullptr, ad0, as1, nullptr, nullptr, (uint2*)xh_d);
    k_multi_dot4<<<cdiv(NM * 32, 256), 256, 0, sC>>>((const float4*)x_m, NM,
        (const float4*)VEC(0,2,1), (const float4*)VEC(0,3,0),
        nullptr, nullptr, ad2, as3, nullptr, nullptr, (uint2*)xh_m);
    cudaEventRecord(evMD, sC);

    // ===== main stream: patient GEMM chain (waits xh_p from sC) =====
    k_cvtW<<<cdiv(HD * HD, 256), 256>>>(W1s + 0 * HD * HD, wt0);
    k_cvtW<<<cdiv(HD * HD, 256), 256>>>(W1s + 2 * HD * HD, wt2);
    cudaStreamWaitEvent(0, evXP, 0);
    {
        dim3 g1(cdiv(NP, 128), 2);
        k_gemm_f16<<<g1, 256>>>(xh_p, wt0, hs0, NP, HD);
    }
    cudaEventRecord(evG0, 0);
    {
        dim3 g1(cdiv(NP, 128), 2);
        k_gemm_f16<<<g1, 256>>>(xh_p, wt2, hs2, NP, HD);
    }

    // ===== stream sB: small-GEMM chain + patient agg (critical consumer) =====
    k_cvtW<<<cdiv(HD * HD, 256), 256, 0, sB>>>(W1s + 1 * HD * HD, wt1);
    k_cvtW<<<cdiv(HD * HD, 256), 256, 0, sB>>>(W1s + 3 * HD * HD, wt3);
    cudaStreamWaitEvent(sB, evMD, 0);
    {
        dim3 g2(cdiv(ND, 128), 2);
        k_gemm_f16<<<g2, 256, 0, sB>>>(xh_d, wt1, hsd, ND, HD);
        dim3 g3(cdiv(NM, 128), 2);
        k_gemm_f16<<<g3, 256, 0, sB>>>(xh_m, wt3, hsm, NM, HD);
    }
    cudaStreamWaitEvent(sB, evA, 0);
    k_agg_dot<4, true><<<cdiv(NP * 32, 256), 256, 0, sB>>>(
        rp_dp, rp_mp, srcs, as1, ad1, as3, ad3,
        (const uint4*)hsd, 16, 0, (const uint4*)hsm, 16, 0,
        b1 + 1 * HD, b1 + 3 * HD,
        VEC(1,1,1), VEC(1,2,0), VEC(1,3,1), u + 1 * HD,
        ad1b, as2b, ad3b, hwp, NP);
    cudaEventRecord(evB, sB);

    // ===== stream sC: disease agg (needs GEMM0 + CSR) =====
    cudaStreamWaitEvent(sC, evG0, 0);
    cudaStreamWaitEvent(sC, evA, 0);
    k_agg_dot<2, false><<<cdiv(ND * 32, 256), 256, 0, sC>>>(
        rp_pd, nullptr, srcs, as0, ad0, nullptr, nullptr,
        (const uint4*)hs0, 16, 0, nullptr, 0, 0,
        b1 + 0 * HD, nullptr,
        VEC(1,1,0), u + 0 * HD, nullptr, nullptr,
        as1b, hwd, nullptr, nullptr, ND);
    cudaEventRecord(evD, sC);

    // ===== main: medicine agg (needs GEMM2 + CSR + multi_dots) =====
    cudaStreamWaitEvent(0, evA, 0);
    cudaStreamWaitEvent(0, evMD, 0);
    k_agg_dot<3, false><<<cdiv(NM * 32, 256), 256>>>(
        rp_pm, nullptr, srcs, as2, ad2, nullptr, nullptr,
        (const uint4*)hs2, 16, 0, nullptr, 0, 0,
        b1 + 2 * HD, nullptr,
        VEC(1,2,1), VEC(1,3,0), u + 2 * HD, nullptr,
        ad2b, as3b, hwm, nullptr, NM);
    cudaEventRecord(evM, 0);

    // ===== sB: s2_m (needs patient agg [as2b, hwp] + medicine agg [ad2b]) =====
    cudaStreamWaitEvent(sB, evM, 0);
    k_s2_m<<<cdiv(NM * 8, 256), 256, 0, sB>>>(rp_pm, srcs, as2b, ad2b, hwp, cb, sm, NM);
    cudaEventRecord(evS, sB);

    // ===== main: s2_p (needs all three aggs) concurrent with s2_m =====
    cudaStreamWaitEvent(0, evB, 0);
    cudaStreamWaitEvent(0, evD, 0);
    k_s2_p<<<cdiv(NP * 8, 256), 256>>>(rp_dp, rp_mp, srcs,
        as1b, ad1b, hwd, as3b, ad3b, hwm, cb, sp, NP);

    // ===== join + head =====
    cudaStreamWaitEvent(0, evS, 0);
    k_final<<<cdiv(ELN, 256), 256>>>(row, col, sp, sm, linb, out, ELN);
    #undef VEC
}